// round 1
// baseline (speedup 1.0000x reference)
#include <cuda_runtime.h>
#include <math.h>

#define BATCH 2
#define SEQ   2048
#define NH    16
#define DH    128
#define DM    2048           // NH*DH
#define NQ    ((size_t)BATCH*NH*SEQ*DH)   // 8388608 elements per Q/K/V buffer

// Scratch (allocation-free per harness rules): 3*32MB QKV + 33MB attn-out
__device__ float g_qkv[3*(size_t)BATCH*NH*SEQ*DH];
__device__ float g_attn[(size_t)BATCH*SEQ*DM];

// ---------------------------------------------------------------------------
// Generic fp32 GEMM: C[M,N] = A[M,K] @ B[K,N] + bias
// 128x128 block tile, BK=8, 256 threads, 8x8 per-thread microtile.
// MODE 0: A = x, writes bias-added result scattered into g_qkv as
//         [part][B][H][S][Dh]  (fused reshape+transpose epilogue)
// MODE 1: A = g_attn (device symbol), writes C row-major with bias.
// ---------------------------------------------------------------------------
template<int MODE>
__global__ __launch_bounds__(256)
void sgemm_kernel(const float* __restrict__ A, const float* __restrict__ B,
                  const float* __restrict__ bias, float* __restrict__ C,
                  int M, int N, int K)
{
    __shared__ float As[8][128];
    __shared__ float Bs[8][128];

    const float* Abase = (MODE == 1) ? (const float*)g_attn : A;

    const int tid      = threadIdx.x;
    const int rowBlock = blockIdx.y * 128;
    const int colBlock = blockIdx.x * 128;

    const int aRow = tid >> 1;          // 0..127
    const int aCol = (tid & 1) * 4;     // 0 or 4
    const int bRow = tid >> 5;          // 0..7
    const int bCol = (tid & 31) * 4;    // 0..124

    const int tx = tid & 15, ty = tid >> 4;
    const int cr = ty * 8,   cc = tx * 8;

    const float* Ap = Abase + (size_t)(rowBlock + aRow) * K + aCol;
    const float* Bp = B + (size_t)bRow * N + colBlock + bCol;

    float acc[8][8] = {};

    for (int k0 = 0; k0 < K; k0 += 8) {
        float4 av = *(const float4*)Ap;
        As[aCol + 0][aRow] = av.x;
        As[aCol + 1][aRow] = av.y;
        As[aCol + 2][aRow] = av.z;
        As[aCol + 3][aRow] = av.w;
        *(float4*)&Bs[bRow][bCol] = *(const float4*)Bp;
        __syncthreads();

        #pragma unroll
        for (int kk = 0; kk < 8; kk++) {
            float a[8], b[8];
            *(float4*)(a)     = *(const float4*)&As[kk][cr];
            *(float4*)(a + 4) = *(const float4*)&As[kk][cr + 4];
            *(float4*)(b)     = *(const float4*)&Bs[kk][cc];
            *(float4*)(b + 4) = *(const float4*)&Bs[kk][cc + 4];
            #pragma unroll
            for (int i = 0; i < 8; i++)
                #pragma unroll
                for (int j = 0; j < 8; j++)
                    acc[i][j] = fmaf(a[i], b[j], acc[i][j]);
        }
        __syncthreads();
        Ap += 8;
        Bp += (size_t)8 * N;
    }

    // bias for this thread's 8 output columns
    float bv[8];
    #pragma unroll
    for (int j = 0; j < 8; j++) bv[j] = bias[colBlock + cc + j];

    if (MODE == 0) {
        // fused scatter: col -> (part, head, d); row -> (batch, seq)
        const int gc0  = colBlock + cc;       // multiple of 8, stays within one head
        const int part = gc0 >> 11;
        const int c2   = gc0 & 2047;
        const int h    = c2 >> 7;
        const int d0   = c2 & 127;
        #pragma unroll
        for (int i = 0; i < 8; i++) {
            const int gr = rowBlock + cr + i;
            const int bb = gr >> 11;
            const int s  = gr & 2047;
            float* dst = g_qkv + (size_t)part * NQ
                       + (((size_t)(bb * NH + h) * SEQ) + s) * DH + d0;
            float4 v0 = make_float4(acc[i][0] + bv[0], acc[i][1] + bv[1],
                                    acc[i][2] + bv[2], acc[i][3] + bv[3]);
            float4 v1 = make_float4(acc[i][4] + bv[4], acc[i][5] + bv[5],
                                    acc[i][6] + bv[6], acc[i][7] + bv[7]);
            *(float4*)(dst)     = v0;
            *(float4*)(dst + 4) = v1;
        }
    } else {
        #pragma unroll
        for (int i = 0; i < 8; i++) {
            const int gr = rowBlock + cr + i;
            float* dst = C + (size_t)gr * N + colBlock + cc;
            float4 v0 = make_float4(acc[i][0] + bv[0], acc[i][1] + bv[1],
                                    acc[i][2] + bv[2], acc[i][3] + bv[3]);
            float4 v1 = make_float4(acc[i][4] + bv[4], acc[i][5] + bv[5],
                                    acc[i][6] + bv[6], acc[i][7] + bv[7]);
            *(float4*)(dst)     = v0;
            *(float4*)(dst + 4) = v1;
        }
    }
}

// ---------------------------------------------------------------------------
// Causal flash attention, fp32.
// Block = one (b, h, 64-query tile). 256 threads (16x16).
// Per thread: 4x4 score tile (rows r0..r0+3, key cols c0..c0+3),
//             4x8 output accumulator (rows r0..r0+3, d-cols oc0..oc0+7).
// Row softmax stats replicated across the 16-lane tx group (shfl.xor reduce).
// smem: Qs[128][64] (d-major), KVs (K as [128][64], then reused as V [64][128]),
//       Ps [64][68] = P^T with pitch 68 (16B aligned rows, conflict-light).
// ---------------------------------------------------------------------------
__global__ __launch_bounds__(256)
void flash_kernel()
{
    extern __shared__ float sm[];
    float* Qs  = sm;                 // 8192 floats
    float* KVs = sm + 128 * 64;      // 8192 floats
    float* Ps  = sm + 2 * 128 * 64;  // 64*68 floats

    const int qt = blockIdx.x, h = blockIdx.y, b = blockIdx.z;
    const int bh = b * NH + h;

    const float* Qp = g_qkv + 0 * NQ + ((size_t)bh * SEQ + qt * 64) * DH;
    const float* Kp = g_qkv + 1 * NQ + (size_t)bh * SEQ * DH;
    const float* Vp = g_qkv + 2 * NQ + (size_t)bh * SEQ * DH;

    const int tid = threadIdx.x;
    const int tx = tid & 15, ty = tid >> 4;
    const int r0 = ty * 4, c0 = tx * 4, oc0 = tx * 8;

    // load Q tile transposed: Qs[d][m]
    for (int u = tid; u < 64 * 32; u += 256) {
        int r = u >> 5, dq = (u & 31) * 4;
        float4 v = *(const float4*)(Qp + r * DH + dq);
        Qs[(dq + 0) * 64 + r] = v.x;
        Qs[(dq + 1) * 64 + r] = v.y;
        Qs[(dq + 2) * 64 + r] = v.z;
        Qs[(dq + 3) * 64 + r] = v.w;
    }

    float m_i[4] = {-1e30f, -1e30f, -1e30f, -1e30f};
    float l_i[4] = {};
    float acc[4][8] = {};
    const float scale = 0.08838834764831845f;  // 1/sqrt(128)

    for (int kt = 0; kt <= qt; kt++) {
        __syncthreads();  // prior V reads done before KVs overwrite (also covers Q load at kt=0)
        const float* Kt = Kp + (size_t)kt * 64 * DH;
        for (int u = tid; u < 64 * 32; u += 256) {
            int r = u >> 5, dq = (u & 31) * 4;
            float4 v = *(const float4*)(Kt + r * DH + dq);
            KVs[(dq + 0) * 64 + r] = v.x;
            KVs[(dq + 1) * 64 + r] = v.y;
            KVs[(dq + 2) * 64 + r] = v.z;
            KVs[(dq + 3) * 64 + r] = v.w;
        }
        __syncthreads();

        // S = Q K^T (4x4 per thread)
        float s[4][4] = {};
        #pragma unroll 8
        for (int d = 0; d < 128; d++) {
            float4 qv = *(const float4*)&Qs[d * 64 + r0];
            float4 kv = *(const float4*)&KVs[d * 64 + c0];
            float qa[4] = {qv.x, qv.y, qv.z, qv.w};
            float ka[4] = {kv.x, kv.y, kv.z, kv.w};
            #pragma unroll
            for (int i = 0; i < 4; i++)
                #pragma unroll
                for (int j = 0; j < 4; j++)
                    s[i][j] = fmaf(qa[i], ka[j], s[i][j]);
        }

        #pragma unroll
        for (int i = 0; i < 4; i++)
            #pragma unroll
            for (int j = 0; j < 4; j++) {
                s[i][j] *= scale;
                if (kt == qt && (c0 + j) > (r0 + i)) s[i][j] = -1e30f;  // causal
            }

        // online softmax
        #pragma unroll
        for (int i = 0; i < 4; i++) {
            float mt = fmaxf(fmaxf(s[i][0], s[i][1]), fmaxf(s[i][2], s[i][3]));
            #pragma unroll
            for (int off = 8; off > 0; off >>= 1)
                mt = fmaxf(mt, __shfl_xor_sync(0xffffffffu, mt, off));
            float mnew  = fmaxf(m_i[i], mt);
            float alpha = __expf(m_i[i] - mnew);
            float rs = 0.f;
            #pragma unroll
            for (int j = 0; j < 4; j++) {
                s[i][j] = __expf(s[i][j] - mnew);
                rs += s[i][j];
            }
            #pragma unroll
            for (int off = 8; off > 0; off >>= 1)
                rs += __shfl_xor_sync(0xffffffffu, rs, off);
            l_i[i] = l_i[i] * alpha + rs;
            m_i[i] = mnew;
            #pragma unroll
            for (int j = 0; j < 8; j++) acc[i][j] *= alpha;
            // store P^T
            #pragma unroll
            for (int j = 0; j < 4; j++)
                Ps[(c0 + j) * 68 + r0 + i] = s[i][j];
        }
        __syncthreads();  // K reads + P writes complete

        // load V tile row-major into KVs
        const float* Vt = Vp + (size_t)kt * 64 * DH;
        for (int u = tid; u < 64 * 32; u += 256) {
            int r = u >> 5, dq = (u & 31) * 4;
            *(float4*)&KVs[r * DH + dq] = *(const float4*)(Vt + r * DH + dq);
        }
        __syncthreads();

        // O += P V  (4x8 per thread)
        #pragma unroll 8
        for (int kk = 0; kk < 64; kk++) {
            float4 pv = *(const float4*)&Ps[kk * 68 + r0];
            float4 v0 = *(const float4*)&KVs[kk * DH + oc0];
            float4 v1 = *(const float4*)&KVs[kk * DH + oc0 + 4];
            float pa[4] = {pv.x, pv.y, pv.z, pv.w};
            float va[8] = {v0.x, v0.y, v0.z, v0.w, v1.x, v1.y, v1.z, v1.w};
            #pragma unroll
            for (int i = 0; i < 4; i++)
                #pragma unroll
                for (int j = 0; j < 8; j++)
                    acc[i][j] = fmaf(pa[i], va[j], acc[i][j]);
        }
    }

    // epilogue: g_attn[b][s][h*128 + d] = acc / l
    #pragma unroll
    for (int i = 0; i < 4; i++) {
        float inv = 1.0f / l_i[i];
        const int row = qt * 64 + r0 + i;
        float* Op = g_attn + ((size_t)b * SEQ + row) * DM + h * DH + oc0;
        float4 v0 = make_float4(acc[i][0] * inv, acc[i][1] * inv,
                                acc[i][2] * inv, acc[i][3] * inv);
        float4 v1 = make_float4(acc[i][4] * inv, acc[i][5] * inv,
                                acc[i][6] * inv, acc[i][7] * inv);
        *(float4*)(Op)     = v0;
        *(float4*)(Op + 4) = v1;
    }
}

// ---------------------------------------------------------------------------
extern "C" void kernel_launch(void* const* d_in, const int* in_sizes, int n_in,
                              void* d_out, int out_size)
{
    const float* x    = (const float*)d_in[0];   // [2, 2048, 2048]
    const float* Wqkv = (const float*)d_in[1];   // [2048, 6144]
    const float* bqkv = (const float*)d_in[2];   // [6144]
    const float* Wout = (const float*)d_in[3];   // [2048, 2048]
    const float* bout = (const float*)d_in[4];   // [2048]
    float* out = (float*)d_out;                  // [2, 2048, 2048]

    const int M = BATCH * SEQ;  // 4096

    // 1) QKV projection, fused bias + reshape/transpose scatter into g_qkv
    {
        dim3 grid((3 * DM) / 128, M / 128);
        sgemm_kernel<0><<<grid, 256>>>(x, Wqkv, bqkv, nullptr, M, 3 * DM, DM);
    }
    // 2) causal flash attention -> g_attn [B, S, D]
    {
        const int smem = (2 * 128 * 64 + 64 * 68) * (int)sizeof(float);  // 82944
        cudaFuncSetAttribute(flash_kernel,
                             cudaFuncAttributeMaxDynamicSharedMemorySize, smem);
        dim3 grid(SEQ / 64, NH, BATCH);
        flash_kernel<<<grid, 256, smem>>>();
    }
    // 3) output projection -> d_out
    {
        dim3 grid(DM / 128, M / 128);
        sgemm_kernel<1><<<grid, 256>>>(nullptr, Wout, bout, out, M, DM, DM);
    }
}

// round 2
// speedup vs baseline: 1.2199x; 1.2199x over previous
#include <cuda_runtime.h>
#include <mma.h>
#include <math.h>

using namespace nvcuda;

#define BATCH 2
#define SEQ   2048
#define NH    16
#define DH    128
#define DM    2048           // NH*DH
#define NQ    ((size_t)BATCH*NH*SEQ*DH)   // elements per Q/K/V buffer

// Scratch (allocation-free per harness rules)
__device__ float g_qkv[3*(size_t)BATCH*NH*SEQ*DH];
__device__ float g_attn[(size_t)BATCH*SEQ*DM];

// ---------------------------------------------------------------------------
// TF32 wmma GEMM: C[M,N] = A[M,K] @ B[K,N] + bias
// 128x128 block tile, BK=32, 256 threads (8 warps, 4x2), warp tile 32x64
// (2x4 wmma m16n16k8 tiles). Register prefetch of next K-slice.
// MODE 0: A = x; epilogue scatters bias-added result into g_qkv as
//         [part][B][H][S][Dh] (fused reshape+transpose).
// MODE 1: A = g_attn; plain row-major C with bias.
// Accuracy: tf32 (rounded via __float_to_tf32 at smem-store time), fp32 accum.
// ---------------------------------------------------------------------------
#define AS_PITCH 40    // 32 + 8 pad (multiple of 8 for wmma ldm, float4-aligned)
#define BS_PITCH 136   // 128 + 8 pad
#define CS_PITCH 136

template<int MODE>
__global__ __launch_bounds__(256)
void gemm_tf32_kernel(const float* __restrict__ A, const float* __restrict__ B,
                      const float* __restrict__ bias, float* __restrict__ C,
                      int M, int N, int K)
{
    extern __shared__ float sm[];
    float* As = sm;                      // [128][AS_PITCH]
    float* Bs = sm + 128 * AS_PITCH;     // [32][BS_PITCH]
    float* Cs = sm;                      // epilogue reuse: [128][CS_PITCH]

    const float* Abase = (MODE == 1) ? (const float*)g_attn : A;

    const int tid  = threadIdx.x;
    const int warp = tid >> 5;
    const int wr   = warp >> 1;   // 0..3  -> M offset 32*wr
    const int wc   = warp & 1;    // 0..1  -> N offset 64*wc
    const int rowBlock = blockIdx.y * 128;
    const int colBlock = blockIdx.x * 128;

    wmma::fragment<wmma::accumulator, 16, 16, 8, float> acc[2][4];
    #pragma unroll
    for (int i = 0; i < 2; i++)
        #pragma unroll
        for (int j = 0; j < 4; j++)
            wmma::fill_fragment(acc[i][j], 0.0f);

    // ---- initial tile load (k0 = 0), converted to tf32 at store ----
    #pragma unroll
    for (int it = 0; it < 4; it++) {
        int u = tid + it * 256;          // A tile: 128 rows x 8 float4
        int row = u >> 3, c = (u & 7) * 4;
        float4 v = *(const float4*)(Abase + (size_t)(rowBlock + row) * K + c);
        v.x = wmma::__float_to_tf32(v.x); v.y = wmma::__float_to_tf32(v.y);
        v.z = wmma::__float_to_tf32(v.z); v.w = wmma::__float_to_tf32(v.w);
        *(float4*)&As[row * AS_PITCH + c] = v;
    }
    #pragma unroll
    for (int it = 0; it < 4; it++) {
        int u = tid + it * 256;          // B tile: 32 rows x 32 float4
        int row = u >> 5, c = (u & 31) * 4;
        float4 v = *(const float4*)(B + (size_t)row * N + colBlock + c);
        v.x = wmma::__float_to_tf32(v.x); v.y = wmma::__float_to_tf32(v.y);
        v.z = wmma::__float_to_tf32(v.z); v.w = wmma::__float_to_tf32(v.w);
        *(float4*)&Bs[row * BS_PITCH + c] = v;
    }
    __syncthreads();

    // ---- main loop over K tiles with register prefetch ----
    for (int k0 = 32; k0 <= K; k0 += 32) {
        float4 aR[4], bR[4];
        const bool more = (k0 < K);
        if (more) {
            #pragma unroll
            for (int it = 0; it < 4; it++) {
                int u = tid + it * 256;
                int row = u >> 3, c = (u & 7) * 4;
                aR[it] = *(const float4*)(Abase + (size_t)(rowBlock + row) * K + k0 + c);
            }
            #pragma unroll
            for (int it = 0; it < 4; it++) {
                int u = tid + it * 256;
                int row = u >> 5, c = (u & 31) * 4;
                bR[it] = *(const float4*)(B + (size_t)(k0 + row) * N + colBlock + c);
            }
        }

        // compute on current smem tile: 4 k-steps of 8
        #pragma unroll
        for (int ks = 0; ks < 4; ks++) {
            wmma::fragment<wmma::matrix_a, 16, 16, 8, wmma::precision::tf32, wmma::row_major> af[2];
            wmma::fragment<wmma::matrix_b, 16, 16, 8, wmma::precision::tf32, wmma::row_major> bf[4];
            #pragma unroll
            for (int i = 0; i < 2; i++)
                wmma::load_matrix_sync(af[i], &As[(wr * 32 + i * 16) * AS_PITCH + ks * 8], AS_PITCH);
            #pragma unroll
            for (int j = 0; j < 4; j++)
                wmma::load_matrix_sync(bf[j], &Bs[(ks * 8) * BS_PITCH + wc * 64 + j * 16], BS_PITCH);
            #pragma unroll
            for (int i = 0; i < 2; i++)
                #pragma unroll
                for (int j = 0; j < 4; j++)
                    wmma::mma_sync(acc[i][j], af[i], bf[j], acc[i][j]);
        }

        if (more) {
            __syncthreads();
            #pragma unroll
            for (int it = 0; it < 4; it++) {
                int u = tid + it * 256;
                int row = u >> 3, c = (u & 7) * 4;
                float4 v = aR[it];
                v.x = wmma::__float_to_tf32(v.x); v.y = wmma::__float_to_tf32(v.y);
                v.z = wmma::__float_to_tf32(v.z); v.w = wmma::__float_to_tf32(v.w);
                *(float4*)&As[row * AS_PITCH + c] = v;
            }
            #pragma unroll
            for (int it = 0; it < 4; it++) {
                int u = tid + it * 256;
                int row = u >> 5, c = (u & 31) * 4;
                float4 v = bR[it];
                v.x = wmma::__float_to_tf32(v.x); v.y = wmma::__float_to_tf32(v.y);
                v.z = wmma::__float_to_tf32(v.z); v.w = wmma::__float_to_tf32(v.w);
                *(float4*)&Bs[row * BS_PITCH + c] = v;
            }
            __syncthreads();
        }
    }

    // ---- epilogue: stage C through smem (reuse As/Bs space), bias + write ----
    __syncthreads();
    #pragma unroll
    for (int i = 0; i < 2; i++)
        #pragma unroll
        for (int j = 0; j < 4; j++)
            wmma::store_matrix_sync(&Cs[(wr * 32 + i * 16) * CS_PITCH + wc * 64 + j * 16],
                                    acc[i][j], CS_PITCH, wmma::mem_row_major);
    __syncthreads();

    for (int it = 0; it < 16; it++) {
        int u = tid + it * 256;              // 128 rows x 32 float4
        int row = u >> 5, c4 = (u & 31) * 4;
        float4 v = *(float4*)&Cs[row * CS_PITCH + c4];
        const int gcol = colBlock + c4;
        v.x += bias[gcol + 0]; v.y += bias[gcol + 1];
        v.z += bias[gcol + 2]; v.w += bias[gcol + 3];
        const int gr = rowBlock + row;
        if (MODE == 0) {
            const int part = gcol >> 11;
            const int c2   = gcol & 2047;
            const int h    = c2 >> 7;
            const int d0   = c2 & 127;
            const int bb   = gr >> 11;
            const int s    = gr & 2047;
            float* dst = g_qkv + (size_t)part * NQ
                       + (((size_t)(bb * NH + h) * SEQ) + s) * DH + d0;
            *(float4*)dst = v;
        } else {
            *(float4*)(C + (size_t)gr * N + gcol) = v;
        }
    }
}

// ---------------------------------------------------------------------------
// Causal flash attention, fp32 (unchanged from round 1 — converts next round).
// ---------------------------------------------------------------------------
__global__ __launch_bounds__(256)
void flash_kernel()
{
    extern __shared__ float smf[];
    float* Qs  = smf;                 // 8192 floats
    float* KVs = smf + 128 * 64;      // 8192 floats
    float* Ps  = smf + 2 * 128 * 64;  // 64*68 floats

    const int qt = blockIdx.x, h = blockIdx.y, b = blockIdx.z;
    const int bh = b * NH + h;

    const float* Qp = g_qkv + 0 * NQ + ((size_t)bh * SEQ + qt * 64) * DH;
    const float* Kp = g_qkv + 1 * NQ + (size_t)bh * SEQ * DH;
    const float* Vp = g_qkv + 2 * NQ + (size_t)bh * SEQ * DH;

    const int tid = threadIdx.x;
    const int tx = tid & 15, ty = tid >> 4;
    const int r0 = ty * 4, c0 = tx * 4, oc0 = tx * 8;

    for (int u = tid; u < 64 * 32; u += 256) {
        int r = u >> 5, dq = (u & 31) * 4;
        float4 v = *(const float4*)(Qp + r * DH + dq);
        Qs[(dq + 0) * 64 + r] = v.x;
        Qs[(dq + 1) * 64 + r] = v.y;
        Qs[(dq + 2) * 64 + r] = v.z;
        Qs[(dq + 3) * 64 + r] = v.w;
    }

    float m_i[4] = {-1e30f, -1e30f, -1e30f, -1e30f};
    float l_i[4] = {};
    float acc[4][8] = {};
    const float scale = 0.08838834764831845f;  // 1/sqrt(128)

    for (int kt = 0; kt <= qt; kt++) {
        __syncthreads();
        const float* Kt = Kp + (size_t)kt * 64 * DH;
        for (int u = tid; u < 64 * 32; u += 256) {
            int r = u >> 5, dq = (u & 31) * 4;
            float4 v = *(const float4*)(Kt + r * DH + dq);
            KVs[(dq + 0) * 64 + r] = v.x;
            KVs[(dq + 1) * 64 + r] = v.y;
            KVs[(dq + 2) * 64 + r] = v.z;
            KVs[(dq + 3) * 64 + r] = v.w;
        }
        __syncthreads();

        float s[4][4] = {};
        #pragma unroll 8
        for (int d = 0; d < 128; d++) {
            float4 qv = *(const float4*)&Qs[d * 64 + r0];
            float4 kv = *(const float4*)&KVs[d * 64 + c0];
            float qa[4] = {qv.x, qv.y, qv.z, qv.w};
            float ka[4] = {kv.x, kv.y, kv.z, kv.w};
            #pragma unroll
            for (int i = 0; i < 4; i++)
                #pragma unroll
                for (int j = 0; j < 4; j++)
                    s[i][j] = fmaf(qa[i], ka[j], s[i][j]);
        }

        #pragma unroll
        for (int i = 0; i < 4; i++)
            #pragma unroll
            for (int j = 0; j < 4; j++) {
                s[i][j] *= scale;
                if (kt == qt && (c0 + j) > (r0 + i)) s[i][j] = -1e30f;
            }

        #pragma unroll
        for (int i = 0; i < 4; i++) {
            float mt = fmaxf(fmaxf(s[i][0], s[i][1]), fmaxf(s[i][2], s[i][3]));
            #pragma unroll
            for (int off = 8; off > 0; off >>= 1)
                mt = fmaxf(mt, __shfl_xor_sync(0xffffffffu, mt, off));
            float mnew  = fmaxf(m_i[i], mt);
            float alpha = __expf(m_i[i] - mnew);
            float rs = 0.f;
            #pragma unroll
            for (int j = 0; j < 4; j++) {
                s[i][j] = __expf(s[i][j] - mnew);
                rs += s[i][j];
            }
            #pragma unroll
            for (int off = 8; off > 0; off >>= 1)
                rs += __shfl_xor_sync(0xffffffffu, rs, off);
            l_i[i] = l_i[i] * alpha + rs;
            m_i[i] = mnew;
            #pragma unroll
            for (int j = 0; j < 8; j++) acc[i][j] *= alpha;
            #pragma unroll
            for (int j = 0; j < 4; j++)
                Ps[(c0 + j) * 68 + r0 + i] = s[i][j];
        }
        __syncthreads();

        const float* Vt = Vp + (size_t)kt * 64 * DH;
        for (int u = tid; u < 64 * 32; u += 256) {
            int r = u >> 5, dq = (u & 31) * 4;
            *(float4*)&KVs[r * DH + dq] = *(const float4*)(Vt + r * DH + dq);
        }
        __syncthreads();

        #pragma unroll 8
        for (int kk = 0; kk < 64; kk++) {
            float4 pv = *(const float4*)&Ps[kk * 68 + r0];
            float4 v0 = *(const float4*)&KVs[kk * DH + oc0];
            float4 v1 = *(const float4*)&KVs[kk * DH + oc0 + 4];
            float pa[4] = {pv.x, pv.y, pv.z, pv.w};
            float va[8] = {v0.x, v0.y, v0.z, v0.w, v1.x, v1.y, v1.z, v1.w};
            #pragma unroll
            for (int i = 0; i < 4; i++)
                #pragma unroll
                for (int j = 0; j < 8; j++)
                    acc[i][j] = fmaf(pa[i], va[j], acc[i][j]);
        }
    }

    #pragma unroll
    for (int i = 0; i < 4; i++) {
        float inv = 1.0f / l_i[i];
        const int row = qt * 64 + r0 + i;
        float* Op = g_attn + ((size_t)b * SEQ + row) * DM + h * DH + oc0;
        float4 v0 = make_float4(acc[i][0] * inv, acc[i][1] * inv,
                                acc[i][2] * inv, acc[i][3] * inv);
        float4 v1 = make_float4(acc[i][4] * inv, acc[i][5] * inv,
                                acc[i][6] * inv, acc[i][7] * inv);
        *(float4*)(Op)     = v0;
        *(float4*)(Op + 4) = v1;
    }
}

// ---------------------------------------------------------------------------
extern "C" void kernel_launch(void* const* d_in, const int* in_sizes, int n_in,
                              void* d_out, int out_size)
{
    const float* x    = (const float*)d_in[0];   // [2, 2048, 2048]
    const float* Wqkv = (const float*)d_in[1];   // [2048, 6144]
    const float* bqkv = (const float*)d_in[2];   // [6144]
    const float* Wout = (const float*)d_in[3];   // [2048, 2048]
    const float* bout = (const float*)d_in[4];   // [2048]
    float* out = (float*)d_out;                  // [2, 2048, 2048]

    const int M = BATCH * SEQ;  // 4096
    const int gemm_smem = 128 * CS_PITCH * (int)sizeof(float);  // 69632 B

    cudaFuncSetAttribute(gemm_tf32_kernel<0>,
                         cudaFuncAttributeMaxDynamicSharedMemorySize, gemm_smem);
    cudaFuncSetAttribute(gemm_tf32_kernel<1>,
                         cudaFuncAttributeMaxDynamicSharedMemorySize, gemm_smem);

    // 1) QKV projection (tf32 tensor cores), fused bias + reshape/transpose
    {
        dim3 grid((3 * DM) / 128, M / 128);
        gemm_tf32_kernel<0><<<grid, 256, gemm_smem>>>(x, Wqkv, bqkv, nullptr, M, 3 * DM, DM);
    }
    // 2) causal flash attention -> g_attn [B, S, D]
    {
        const int smem = (2 * 128 * 64 + 64 * 68) * (int)sizeof(float);  // 82944
        cudaFuncSetAttribute(flash_kernel,
                             cudaFuncAttributeMaxDynamicSharedMemorySize, smem);
        dim3 grid(SEQ / 64, NH, BATCH);
        flash_kernel<<<grid, 256, smem>>>();
    }
    // 3) output projection (tf32 tensor cores) -> d_out
    {
        dim3 grid(DM / 128, M / 128);
        gemm_tf32_kernel<1><<<grid, 256, gemm_smem>>>(nullptr, Wout, bout, out, M, DM, DM);
    }
}

// round 3
// speedup vs baseline: 1.5422x; 1.2642x over previous
#include <cuda_runtime.h>
#include <mma.h>
#include <math.h>

using namespace nvcuda;

#define BATCH 2
#define SEQ   2048
#define NH    16
#define DH    128
#define DM    2048           // NH*DH
#define NQ    ((size_t)BATCH*NH*SEQ*DH)   // elements per Q/K/V buffer

// Scratch (allocation-free per harness rules)
__device__ float g_qkv[3*(size_t)BATCH*NH*SEQ*DH];
__device__ float g_attn[(size_t)BATCH*SEQ*DM];

// ---------------------------------------------------------------------------
// TF32 wmma GEMM: C[M,N] = A[M,K] @ B[K,N] + bias   (unchanged from round 2)
// ---------------------------------------------------------------------------
#define AS_PITCH 40
#define BS_PITCH 136
#define CS_PITCH 136

template<int MODE>
__global__ __launch_bounds__(256)
void gemm_tf32_kernel(const float* __restrict__ A, const float* __restrict__ B,
                      const float* __restrict__ bias, float* __restrict__ C,
                      int M, int N, int K)
{
    extern __shared__ float sm[];
    float* As = sm;                      // [128][AS_PITCH]
    float* Bs = sm + 128 * AS_PITCH;     // [32][BS_PITCH]
    float* Cs = sm;                      // epilogue reuse: [128][CS_PITCH]

    const float* Abase = (MODE == 1) ? (const float*)g_attn : A;

    const int tid  = threadIdx.x;
    const int warp = tid >> 5;
    const int wr   = warp >> 1;
    const int wc   = warp & 1;
    const int rowBlock = blockIdx.y * 128;
    const int colBlock = blockIdx.x * 128;

    wmma::fragment<wmma::accumulator, 16, 16, 8, float> acc[2][4];
    #pragma unroll
    for (int i = 0; i < 2; i++)
        #pragma unroll
        for (int j = 0; j < 4; j++)
            wmma::fill_fragment(acc[i][j], 0.0f);

    #pragma unroll
    for (int it = 0; it < 4; it++) {
        int u = tid + it * 256;
        int row = u >> 3, c = (u & 7) * 4;
        float4 v = *(const float4*)(Abase + (size_t)(rowBlock + row) * K + c);
        v.x = wmma::__float_to_tf32(v.x); v.y = wmma::__float_to_tf32(v.y);
        v.z = wmma::__float_to_tf32(v.z); v.w = wmma::__float_to_tf32(v.w);
        *(float4*)&As[row * AS_PITCH + c] = v;
    }
    #pragma unroll
    for (int it = 0; it < 4; it++) {
        int u = tid + it * 256;
        int row = u >> 5, c = (u & 31) * 4;
        float4 v = *(const float4*)(B + (size_t)row * N + colBlock + c);
        v.x = wmma::__float_to_tf32(v.x); v.y = wmma::__float_to_tf32(v.y);
        v.z = wmma::__float_to_tf32(v.z); v.w = wmma::__float_to_tf32(v.w);
        *(float4*)&Bs[row * BS_PITCH + c] = v;
    }
    __syncthreads();

    for (int k0 = 32; k0 <= K; k0 += 32) {
        float4 aR[4], bR[4];
        const bool more = (k0 < K);
        if (more) {
            #pragma unroll
            for (int it = 0; it < 4; it++) {
                int u = tid + it * 256;
                int row = u >> 3, c = (u & 7) * 4;
                aR[it] = *(const float4*)(Abase + (size_t)(rowBlock + row) * K + k0 + c);
            }
            #pragma unroll
            for (int it = 0; it < 4; it++) {
                int u = tid + it * 256;
                int row = u >> 5, c = (u & 31) * 4;
                bR[it] = *(const float4*)(B + (size_t)(k0 + row) * N + colBlock + c);
            }
        }

        #pragma unroll
        for (int ks = 0; ks < 4; ks++) {
            wmma::fragment<wmma::matrix_a, 16, 16, 8, wmma::precision::tf32, wmma::row_major> af[2];
            wmma::fragment<wmma::matrix_b, 16, 16, 8, wmma::precision::tf32, wmma::row_major> bf[4];
            #pragma unroll
            for (int i = 0; i < 2; i++)
                wmma::load_matrix_sync(af[i], &As[(wr * 32 + i * 16) * AS_PITCH + ks * 8], AS_PITCH);
            #pragma unroll
            for (int j = 0; j < 4; j++)
                wmma::load_matrix_sync(bf[j], &Bs[(ks * 8) * BS_PITCH + wc * 64 + j * 16], BS_PITCH);
            #pragma unroll
            for (int i = 0; i < 2; i++)
                #pragma unroll
                for (int j = 0; j < 4; j++)
                    wmma::mma_sync(acc[i][j], af[i], bf[j], acc[i][j]);
        }

        if (more) {
            __syncthreads();
            #pragma unroll
            for (int it = 0; it < 4; it++) {
                int u = tid + it * 256;
                int row = u >> 3, c = (u & 7) * 4;
                float4 v = aR[it];
                v.x = wmma::__float_to_tf32(v.x); v.y = wmma::__float_to_tf32(v.y);
                v.z = wmma::__float_to_tf32(v.z); v.w = wmma::__float_to_tf32(v.w);
                *(float4*)&As[row * AS_PITCH + c] = v;
            }
            #pragma unroll
            for (int it = 0; it < 4; it++) {
                int u = tid + it * 256;
                int row = u >> 5, c = (u & 31) * 4;
                float4 v = bR[it];
                v.x = wmma::__float_to_tf32(v.x); v.y = wmma::__float_to_tf32(v.y);
                v.z = wmma::__float_to_tf32(v.z); v.w = wmma::__float_to_tf32(v.w);
                *(float4*)&Bs[row * BS_PITCH + c] = v;
            }
            __syncthreads();
        }
    }

    __syncthreads();
    #pragma unroll
    for (int i = 0; i < 2; i++)
        #pragma unroll
        for (int j = 0; j < 4; j++)
            wmma::store_matrix_sync(&Cs[(wr * 32 + i * 16) * CS_PITCH + wc * 64 + j * 16],
                                    acc[i][j], CS_PITCH, wmma::mem_row_major);
    __syncthreads();

    for (int it = 0; it < 16; it++) {
        int u = tid + it * 256;
        int row = u >> 5, c4 = (u & 31) * 4;
        float4 v = *(float4*)&Cs[row * CS_PITCH + c4];
        const int gcol = colBlock + c4;
        v.x += bias[gcol + 0]; v.y += bias[gcol + 1];
        v.z += bias[gcol + 2]; v.w += bias[gcol + 3];
        const int gr = rowBlock + row;
        if (MODE == 0) {
            const int part = gcol >> 11;
            const int c2   = gcol & 2047;
            const int h    = c2 >> 7;
            const int d0   = c2 & 127;
            const int bb   = gr >> 11;
            const int s    = gr & 2047;
            float* dst = g_qkv + (size_t)part * NQ
                       + (((size_t)(bb * NH + h) * SEQ) + s) * DH + d0;
            *(float4*)dst = v;
        } else {
            *(float4*)(C + (size_t)gr * N + gcol) = v;
        }
    }
}

// ---------------------------------------------------------------------------
// Causal flash attention with tf32 wmma for both GEMMs; fp32 softmax/stats.
// CTA = one (b, h, 64-query tile). 256 threads (8 warps, 4x2 warp grid).
// smem: Qs/Ks/Vs/Os [64][132] (tf32 / fp32-O), Ss [64][68], m/l [64].
// S gemm:  Q(row-major, ld 132) x K(col-major, ld 132) -> Ss
// softmax: 4 threads/row, in-place exp -> P(tf32); alpha-rescale of Os rows.
// PV gemm: acc frags loaded from Os, accumulate P(Ss) x V(Vs), store back.
// ---------------------------------------------------------------------------
#define FP 132   // Q/K/V/O pitch
#define SP 68    // S/P pitch

__global__ __launch_bounds__(256)
void flash_kernel()
{
    extern __shared__ float smf[];
    float* Qs = smf;                 // 64*132
    float* Ks = smf + 8448;
    float* Vs = smf + 16896;
    float* Os = smf + 25344;
    float* Ss = smf + 33792;         // 64*68
    float* mrow = smf + 38144;       // 64
    float* lrow = smf + 38208;       // 64

    const int qt = blockIdx.x, h = blockIdx.y, b = blockIdx.z;
    const int bh = b * NH + h;

    const float* Qp = g_qkv + 0 * NQ + ((size_t)bh * SEQ + qt * 64) * DH;
    const float* Kp = g_qkv + 1 * NQ + (size_t)bh * SEQ * DH;
    const float* Vp = g_qkv + 2 * NQ + (size_t)bh * SEQ * DH;

    const int tid  = threadIdx.x;
    const int warp = tid >> 5;
    const int wr   = warp >> 1;   // 0..3 -> 16-row band
    const int wc   = warp & 1;    // 0..1

    const float scale = 0.08838834764831845f;  // 1/sqrt(128)

    // init: load Q (scaled + tf32), zero O, init stats
    #pragma unroll
    for (int it = 0; it < 8; it++) {
        int u = tid + it * 256;          // 64 rows x 32 float4
        int r = u >> 5, c = (u & 31) * 4;
        float4 v = *(const float4*)(Qp + r * DH + c);
        v.x = wmma::__float_to_tf32(v.x * scale);
        v.y = wmma::__float_to_tf32(v.y * scale);
        v.z = wmma::__float_to_tf32(v.z * scale);
        v.w = wmma::__float_to_tf32(v.w * scale);
        *(float4*)&Qs[r * FP + c] = v;
        *(float4*)&Os[r * FP + c] = make_float4(0.f, 0.f, 0.f, 0.f);
    }
    if (tid < 64) { mrow[tid] = -1e30f; lrow[tid] = 0.f; }

    for (int kt = 0; kt <= qt; kt++) {
        __syncthreads();   // prev-iter Ss/Vs reads + Q/O init done
        const float* Kt = Kp + (size_t)kt * 64 * DH;
        const float* Vt = Vp + (size_t)kt * 64 * DH;
        #pragma unroll
        for (int it = 0; it < 8; it++) {
            int u = tid + it * 256;
            int r = u >> 5, c = (u & 31) * 4;
            float4 kv = *(const float4*)(Kt + r * DH + c);
            kv.x = wmma::__float_to_tf32(kv.x); kv.y = wmma::__float_to_tf32(kv.y);
            kv.z = wmma::__float_to_tf32(kv.z); kv.w = wmma::__float_to_tf32(kv.w);
            *(float4*)&Ks[r * FP + c] = kv;
            float4 vv = *(const float4*)(Vt + r * DH + c);
            vv.x = wmma::__float_to_tf32(vv.x); vv.y = wmma::__float_to_tf32(vv.y);
            vv.z = wmma::__float_to_tf32(vv.z); vv.w = wmma::__float_to_tf32(vv.w);
            *(float4*)&Vs[r * FP + c] = vv;
        }
        __syncthreads();

        // ---- S = (Q*scale) K^T : warp computes 16x32 (2 tiles), k=128 ----
        {
            wmma::fragment<wmma::accumulator, 16, 16, 8, float> sacc[2];
            wmma::fill_fragment(sacc[0], 0.0f);
            wmma::fill_fragment(sacc[1], 0.0f);
            #pragma unroll
            for (int ks = 0; ks < 16; ks++) {
                wmma::fragment<wmma::matrix_a, 16, 16, 8, wmma::precision::tf32, wmma::row_major> af;
                wmma::fragment<wmma::matrix_b, 16, 16, 8, wmma::precision::tf32, wmma::col_major> bf[2];
                wmma::load_matrix_sync(af, &Qs[(wr * 16) * FP + ks * 8], FP);
                #pragma unroll
                for (int j = 0; j < 2; j++)
                    wmma::load_matrix_sync(bf[j], &Ks[(wc * 32 + j * 16) * FP + ks * 8], FP);
                #pragma unroll
                for (int j = 0; j < 2; j++)
                    wmma::mma_sync(sacc[j], af, bf[j], sacc[j]);
            }
            #pragma unroll
            for (int j = 0; j < 2; j++)
                wmma::store_matrix_sync(&Ss[(wr * 16) * SP + wc * 32 + j * 16],
                                        sacc[j], SP, wmma::mem_row_major);
        }
        __syncthreads();

        // ---- softmax: 4 threads per row, 16 cols each; rescale O rows ----
        {
            const int row = tid >> 2;
            const int q   = tid & 3;
            const int c0  = q * 16;
            float s[16];
            #pragma unroll
            for (int j = 0; j < 16; j++) {
                s[j] = Ss[row * SP + c0 + j];
                if (kt == qt && (c0 + j) > row) s[j] = -1e30f;
            }
            float mt = s[0];
            #pragma unroll
            for (int j = 1; j < 16; j++) mt = fmaxf(mt, s[j]);
            mt = fmaxf(mt, __shfl_xor_sync(0xffffffffu, mt, 1));
            mt = fmaxf(mt, __shfl_xor_sync(0xffffffffu, mt, 2));
            const float m_old = mrow[row];
            const float mnew  = fmaxf(m_old, mt);
            const float alpha = __expf(m_old - mnew);
            float rs = 0.f;
            #pragma unroll
            for (int j = 0; j < 16; j++) {
                float p = __expf(s[j] - mnew);
                rs += p;
                Ss[row * SP + c0 + j] = wmma::__float_to_tf32(p);
            }
            rs += __shfl_xor_sync(0xffffffffu, rs, 1);
            rs += __shfl_xor_sync(0xffffffffu, rs, 2);
            if (q == 0) {
                lrow[row] = lrow[row] * alpha + rs;
                mrow[row] = mnew;
            }
            // rescale O row: this thread owns cols q*32 .. q*32+31
            float* Orow = Os + row * FP + q * 32;
            #pragma unroll
            for (int j = 0; j < 8; j++) {
                float4 v = *(float4*)(Orow + j * 4);
                v.x *= alpha; v.y *= alpha; v.z *= alpha; v.w *= alpha;
                *(float4*)(Orow + j * 4) = v;
            }
        }
        __syncthreads();

        // ---- O += P V : warp computes 16x64 (4 tiles), k=64 ----
        {
            wmma::fragment<wmma::accumulator, 16, 16, 8, float> oacc[4];
            #pragma unroll
            for (int j = 0; j < 4; j++)
                wmma::load_matrix_sync(oacc[j], &Os[(wr * 16) * FP + wc * 64 + j * 16],
                                       FP, wmma::mem_row_major);
            #pragma unroll
            for (int ks = 0; ks < 8; ks++) {
                wmma::fragment<wmma::matrix_a, 16, 16, 8, wmma::precision::tf32, wmma::row_major> pf;
                wmma::fragment<wmma::matrix_b, 16, 16, 8, wmma::precision::tf32, wmma::row_major> vf[4];
                wmma::load_matrix_sync(pf, &Ss[(wr * 16) * SP + ks * 8], SP);
                #pragma unroll
                for (int j = 0; j < 4; j++)
                    wmma::load_matrix_sync(vf[j], &Vs[(ks * 8) * FP + wc * 64 + j * 16], FP);
                #pragma unroll
                for (int j = 0; j < 4; j++)
                    wmma::mma_sync(oacc[j], pf, vf[j], oacc[j]);
            }
            #pragma unroll
            for (int j = 0; j < 4; j++)
                wmma::store_matrix_sync(&Os[(wr * 16) * FP + wc * 64 + j * 16],
                                        oacc[j], FP, wmma::mem_row_major);
        }
    }
    __syncthreads();

    // epilogue: g_attn[b][s][h*128 + d] = Os / l
    #pragma unroll
    for (int it = 0; it < 8; it++) {
        int u = tid + it * 256;
        int r = u >> 5, c = (u & 31) * 4;
        const float inv = 1.0f / lrow[r];
        float4 v = *(float4*)&Os[r * FP + c];
        v.x *= inv; v.y *= inv; v.z *= inv; v.w *= inv;
        float* Op = g_attn + ((size_t)b * SEQ + qt * 64 + r) * DM + h * DH + c;
        *(float4*)Op = v;
    }
}

// ---------------------------------------------------------------------------
extern "C" void kernel_launch(void* const* d_in, const int* in_sizes, int n_in,
                              void* d_out, int out_size)
{
    const float* x    = (const float*)d_in[0];   // [2, 2048, 2048]
    const float* Wqkv = (const float*)d_in[1];   // [2048, 6144]
    const float* bqkv = (const float*)d_in[2];   // [6144]
    const float* Wout = (const float*)d_in[3];   // [2048, 2048]
    const float* bout = (const float*)d_in[4];   // [2048]
    float* out = (float*)d_out;                  // [2, 2048, 2048]

    const int M = BATCH * SEQ;  // 4096
    const int gemm_smem = 128 * CS_PITCH * (int)sizeof(float);  // 69632 B

    cudaFuncSetAttribute(gemm_tf32_kernel<0>,
                         cudaFuncAttributeMaxDynamicSharedMemorySize, gemm_smem);
    cudaFuncSetAttribute(gemm_tf32_kernel<1>,
                         cudaFuncAttributeMaxDynamicSharedMemorySize, gemm_smem);

    // 1) QKV projection (tf32), fused bias + reshape/transpose scatter
    {
        dim3 grid((3 * DM) / 128, M / 128);
        gemm_tf32_kernel<0><<<grid, 256, gemm_smem>>>(x, Wqkv, bqkv, nullptr, M, 3 * DM, DM);
    }
    // 2) causal flash attention (tf32 wmma) -> g_attn [B, S, D]
    {
        const int smem = 38272 * (int)sizeof(float);  // 153088 B
        cudaFuncSetAttribute(flash_kernel,
                             cudaFuncAttributeMaxDynamicSharedMemorySize, smem);
        dim3 grid(SEQ / 64, NH, BATCH);
        flash_kernel<<<grid, 256, smem>>>();
    }
    // 3) output projection (tf32) -> d_out
    {
        dim3 grid(DM / 128, M / 128);
        gemm_tf32_kernel<1><<<grid, 256, gemm_smem>>>(nullptr, Wout, bout, out, M, DM, DM);
    }
}

// round 4
// speedup vs baseline: 1.8368x; 1.1910x over previous
#include <cuda_runtime.h>
#include <mma.h>
#include <math.h>
#include <stdint.h>

using namespace nvcuda;

#define BATCH 2
#define SEQ   2048
#define NH    16
#define DH    128
#define DM    2048           // NH*DH
#define NQ    ((size_t)BATCH*NH*SEQ*DH)

// Scratch (allocation-free per harness rules)
__device__ float g_qkv[3*(size_t)BATCH*NH*SEQ*DH];
__device__ float g_attn[(size_t)BATCH*SEQ*DM];
// tf32-pre-rounded copies of GEMM inputs
__device__ float g_xt[(size_t)BATCH*SEQ*DM];      // x
__device__ float g_wq[(size_t)DM*3*DM];           // W_qkv
__device__ float g_wo[(size_t)DM*DM];             // W_out

// ---------------------------------------------------------------------------
__device__ __forceinline__ uint32_t smem_u32(const void* p) {
    return (uint32_t)__cvta_generic_to_shared(p);
}
#define CP_ASYNC16(dst_u32, src_ptr) \
    asm volatile("cp.async.cg.shared.global [%0], [%1], 16;" :: "r"(dst_u32), "l"(src_ptr))
#define CP_COMMIT()   asm volatile("cp.async.commit_group;")
#define CP_WAIT(n)    asm volatile("cp.async.wait_group %0;" :: "n"(n))

// ---------------------------------------------------------------------------
// tf32 pre-rounding pass (grid-stride over float4)
// ---------------------------------------------------------------------------
__global__ void cvt_tf32_kernel(const float* __restrict__ in,
                                float* __restrict__ out, int n4)
{
    int i = blockIdx.x * blockDim.x + threadIdx.x;
    if (i < n4) {
        float4 v = ((const float4*)in)[i];
        v.x = wmma::__float_to_tf32(v.x); v.y = wmma::__float_to_tf32(v.y);
        v.z = wmma::__float_to_tf32(v.z); v.w = wmma::__float_to_tf32(v.w);
        ((float4*)out)[i] = v;
    }
}

// ---------------------------------------------------------------------------
// TF32 wmma GEMM with cp.async double-buffered pipeline.
// C[M,N] = A[M,K] @ B[K,N] + bias. Inputs already tf32-rounded.
// 128x128 tile, BK=32, 256 threads (8 warps 4x2), warp tile 32x64.
// MODE 0: A=g_xt, scatter epilogue into g_qkv [part][B][H][S][Dh].
// MODE 1: A=g_attn, row-major C.
// ---------------------------------------------------------------------------
#define AS_PITCH 40
#define BS_PITCH 136
#define CS_PITCH 136
#define STAGE_F  (128*AS_PITCH + 32*BS_PITCH)   // floats per stage = 9472

template<int MODE>
__global__ __launch_bounds__(256, 2)
void gemm_tf32_kernel(const float* __restrict__ Aglob, const float* __restrict__ B,
                      const float* __restrict__ bias, float* __restrict__ C,
                      int M, int N, int K)
{
    extern __shared__ float sm[];
    // stage s: As = sm + s*STAGE_F, Bs = sm + s*STAGE_F + 128*AS_PITCH
    float* Cs = sm;   // epilogue reuse (128*136 = 17408 floats <= 2*STAGE_F)

    const float* Abase = (MODE == 1) ? (const float*)g_attn : Aglob;

    const int tid  = threadIdx.x;
    const int warp = tid >> 5;
    const int wr   = warp >> 1;
    const int wc   = warp & 1;
    const int rowBlock = blockIdx.y * 128;
    const int colBlock = blockIdx.x * 128;

    // per-thread load coordinates (4 float4 each for A and B)
    const int aRow0 = tid >> 3;            // +32 per it
    const int aCol  = (tid & 7) * 4;
    const int bRow0 = tid >> 5;            // +8 per it
    const int bCol  = (tid & 31) * 4;

    const float* Asrc = Abase + (size_t)(rowBlock + aRow0) * K + aCol;
    const float* Bsrc = B + (size_t)bRow0 * N + colBlock + bCol;

    const uint32_t smBase = smem_u32(sm);
    const uint32_t aOffB  = (uint32_t)((aRow0 * AS_PITCH + aCol) * 4);
    const uint32_t bOffB  = (uint32_t)((128 * AS_PITCH + bRow0 * BS_PITCH + bCol) * 4);

    wmma::fragment<wmma::accumulator, 16, 16, 8, float> acc[2][4];
    #pragma unroll
    for (int i = 0; i < 2; i++)
        #pragma unroll
        for (int j = 0; j < 4; j++)
            wmma::fill_fragment(acc[i][j], 0.0f);

    const int NIT = K >> 5;   // K/32

    // issue helper (macro-ish lambda)
    auto issue = [&](int k0, int s) {
        const uint32_t sb = smBase + (uint32_t)(s * STAGE_F * 4);
        #pragma unroll
        for (int it = 0; it < 4; it++) {
            CP_ASYNC16(sb + aOffB + (uint32_t)(it * 32 * AS_PITCH * 4),
                       Asrc + (size_t)(it * 32) * K + k0);
        }
        #pragma unroll
        for (int it = 0; it < 4; it++) {
            CP_ASYNC16(sb + bOffB + (uint32_t)(it * 8 * BS_PITCH * 4),
                       Bsrc + (size_t)(k0 + it * 8) * N);
        }
    };

    issue(0, 0);
    CP_COMMIT();

    int buf = 0;
    for (int it = 0; it < NIT; it++) {
        if (it + 1 < NIT) {
            issue((it + 1) << 5, buf ^ 1);
            CP_COMMIT();
            CP_WAIT(1);
        } else {
            CP_WAIT(0);
        }
        __syncthreads();

        const float* As = sm + buf * STAGE_F;
        const float* Bs = As + 128 * AS_PITCH;
        #pragma unroll
        for (int ks = 0; ks < 4; ks++) {
            wmma::fragment<wmma::matrix_a, 16, 16, 8, wmma::precision::tf32, wmma::row_major> af[2];
            wmma::fragment<wmma::matrix_b, 16, 16, 8, wmma::precision::tf32, wmma::row_major> bf[4];
            #pragma unroll
            for (int i = 0; i < 2; i++)
                wmma::load_matrix_sync(af[i], &As[(wr * 32 + i * 16) * AS_PITCH + ks * 8], AS_PITCH);
            #pragma unroll
            for (int j = 0; j < 4; j++)
                wmma::load_matrix_sync(bf[j], &Bs[(ks * 8) * BS_PITCH + wc * 64 + j * 16], BS_PITCH);
            #pragma unroll
            for (int i = 0; i < 2; i++)
                #pragma unroll
                for (int j = 0; j < 4; j++)
                    wmma::mma_sync(acc[i][j], af[i], bf[j], acc[i][j]);
        }
        __syncthreads();   // guard buffer reuse before next issue overwrites it
        buf ^= 1;
    }

    // ---- epilogue: stage C through smem, bias + write ----
    #pragma unroll
    for (int i = 0; i < 2; i++)
        #pragma unroll
        for (int j = 0; j < 4; j++)
            wmma::store_matrix_sync(&Cs[(wr * 32 + i * 16) * CS_PITCH + wc * 64 + j * 16],
                                    acc[i][j], CS_PITCH, wmma::mem_row_major);
    __syncthreads();

    #pragma unroll
    for (int it = 0; it < 16; it++) {
        int u = tid + it * 256;
        int row = u >> 5, c4 = (u & 31) * 4;
        float4 v = *(float4*)&Cs[row * CS_PITCH + c4];
        const int gcol = colBlock + c4;
        v.x += bias[gcol + 0]; v.y += bias[gcol + 1];
        v.z += bias[gcol + 2]; v.w += bias[gcol + 3];
        const int gr = rowBlock + row;
        if (MODE == 0) {
            const int part = gcol >> 11;
            const int c2   = gcol & 2047;
            const int h    = c2 >> 7;
            const int d0   = c2 & 127;
            const int bb   = gr >> 11;
            const int s    = gr & 2047;
            float* dst = g_qkv + (size_t)part * NQ
                       + (((size_t)(bb * NH + h) * SEQ) + s) * DH + d0;
            *(float4*)dst = v;
        } else {
            *(float4*)(C + (size_t)gr * N + gcol) = v;
        }
    }
}

// ---------------------------------------------------------------------------
// Causal flash attention, tf32 wmma (unchanged from round 3 except the
// epilogue rounds g_attn to tf32 so the out-proj GEMM can skip conversion).
// ---------------------------------------------------------------------------
#define FP 132
#define SP 68

__global__ __launch_bounds__(256)
void flash_kernel()
{
    extern __shared__ float smf[];
    float* Qs = smf;
    float* Ks = smf + 8448;
    float* Vs = smf + 16896;
    float* Os = smf + 25344;
    float* Ss = smf + 33792;
    float* mrow = smf + 38144;
    float* lrow = smf + 38208;

    const int qt = blockIdx.x, h = blockIdx.y, b = blockIdx.z;
    const int bh = b * NH + h;

    const float* Qp = g_qkv + 0 * NQ + ((size_t)bh * SEQ + qt * 64) * DH;
    const float* Kp = g_qkv + 1 * NQ + (size_t)bh * SEQ * DH;
    const float* Vp = g_qkv + 2 * NQ + (size_t)bh * SEQ * DH;

    const int tid  = threadIdx.x;
    const int warp = tid >> 5;
    const int wr   = warp >> 1;
    const int wc   = warp & 1;

    const float scale = 0.08838834764831845f;

    #pragma unroll
    for (int it = 0; it < 8; it++) {
        int u = tid + it * 256;
        int r = u >> 5, c = (u & 31) * 4;
        float4 v = *(const float4*)(Qp + r * DH + c);
        v.x = wmma::__float_to_tf32(v.x * scale);
        v.y = wmma::__float_to_tf32(v.y * scale);
        v.z = wmma::__float_to_tf32(v.z * scale);
        v.w = wmma::__float_to_tf32(v.w * scale);
        *(float4*)&Qs[r * FP + c] = v;
        *(float4*)&Os[r * FP + c] = make_float4(0.f, 0.f, 0.f, 0.f);
    }
    if (tid < 64) { mrow[tid] = -1e30f; lrow[tid] = 0.f; }

    for (int kt = 0; kt <= qt; kt++) {
        __syncthreads();
        const float* Kt = Kp + (size_t)kt * 64 * DH;
        const float* Vt = Vp + (size_t)kt * 64 * DH;
        #pragma unroll
        for (int it = 0; it < 8; it++) {
            int u = tid + it * 256;
            int r = u >> 5, c = (u & 31) * 4;
            float4 kv = *(const float4*)(Kt + r * DH + c);
            kv.x = wmma::__float_to_tf32(kv.x); kv.y = wmma::__float_to_tf32(kv.y);
            kv.z = wmma::__float_to_tf32(kv.z); kv.w = wmma::__float_to_tf32(kv.w);
            *(float4*)&Ks[r * FP + c] = kv;
            float4 vv = *(const float4*)(Vt + r * DH + c);
            vv.x = wmma::__float_to_tf32(vv.x); vv.y = wmma::__float_to_tf32(vv.y);
            vv.z = wmma::__float_to_tf32(vv.z); vv.w = wmma::__float_to_tf32(vv.w);
            *(float4*)&Vs[r * FP + c] = vv;
        }
        __syncthreads();

        {
            wmma::fragment<wmma::accumulator, 16, 16, 8, float> sacc[2];
            wmma::fill_fragment(sacc[0], 0.0f);
            wmma::fill_fragment(sacc[1], 0.0f);
            #pragma unroll
            for (int ks = 0; ks < 16; ks++) {
                wmma::fragment<wmma::matrix_a, 16, 16, 8, wmma::precision::tf32, wmma::row_major> af;
                wmma::fragment<wmma::matrix_b, 16, 16, 8, wmma::precision::tf32, wmma::col_major> bf[2];
                wmma::load_matrix_sync(af, &Qs[(wr * 16) * FP + ks * 8], FP);
                #pragma unroll
                for (int j = 0; j < 2; j++)
                    wmma::load_matrix_sync(bf[j], &Ks[(wc * 32 + j * 16) * FP + ks * 8], FP);
                #pragma unroll
                for (int j = 0; j < 2; j++)
                    wmma::mma_sync(sacc[j], af, bf[j], sacc[j]);
            }
            #pragma unroll
            for (int j = 0; j < 2; j++)
                wmma::store_matrix_sync(&Ss[(wr * 16) * SP + wc * 32 + j * 16],
                                        sacc[j], SP, wmma::mem_row_major);
        }
        __syncthreads();

        {
            const int row = tid >> 2;
            const int q   = tid & 3;
            const int c0  = q * 16;
            float s[16];
            #pragma unroll
            for (int j = 0; j < 16; j++) {
                s[j] = Ss[row * SP + c0 + j];
                if (kt == qt && (c0 + j) > row) s[j] = -1e30f;
            }
            float mt = s[0];
            #pragma unroll
            for (int j = 1; j < 16; j++) mt = fmaxf(mt, s[j]);
            mt = fmaxf(mt, __shfl_xor_sync(0xffffffffu, mt, 1));
            mt = fmaxf(mt, __shfl_xor_sync(0xffffffffu, mt, 2));
            const float m_old = mrow[row];
            const float mnew  = fmaxf(m_old, mt);
            const float alpha = __expf(m_old - mnew);
            float rs = 0.f;
            #pragma unroll
            for (int j = 0; j < 16; j++) {
                float p = __expf(s[j] - mnew);
                rs += p;
                Ss[row * SP + c0 + j] = wmma::__float_to_tf32(p);
            }
            rs += __shfl_xor_sync(0xffffffffu, rs, 1);
            rs += __shfl_xor_sync(0xffffffffu, rs, 2);
            if (q == 0) {
                lrow[row] = lrow[row] * alpha + rs;
                mrow[row] = mnew;
            }
            float* Orow = Os + row * FP + q * 32;
            #pragma unroll
            for (int j = 0; j < 8; j++) {
                float4 v = *(float4*)(Orow + j * 4);
                v.x *= alpha; v.y *= alpha; v.z *= alpha; v.w *= alpha;
                *(float4*)(Orow + j * 4) = v;
            }
        }
        __syncthreads();

        {
            wmma::fragment<wmma::accumulator, 16, 16, 8, float> oacc[4];
            #pragma unroll
            for (int j = 0; j < 4; j++)
                wmma::load_matrix_sync(oacc[j], &Os[(wr * 16) * FP + wc * 64 + j * 16],
                                       FP, wmma::mem_row_major);
            #pragma unroll
            for (int ks = 0; ks < 8; ks++) {
                wmma::fragment<wmma::matrix_a, 16, 16, 8, wmma::precision::tf32, wmma::row_major> pf;
                wmma::fragment<wmma::matrix_b, 16, 16, 8, wmma::precision::tf32, wmma::row_major> vf[4];
                wmma::load_matrix_sync(pf, &Ss[(wr * 16) * SP + ks * 8], SP);
                #pragma unroll
                for (int j = 0; j < 4; j++)
                    wmma::load_matrix_sync(vf[j], &Vs[(ks * 8) * FP + wc * 64 + j * 16], FP);
                #pragma unroll
                for (int j = 0; j < 4; j++)
                    wmma::mma_sync(oacc[j], pf, vf[j], oacc[j]);
            }
            #pragma unroll
            for (int j = 0; j < 4; j++)
                wmma::store_matrix_sync(&Os[(wr * 16) * FP + wc * 64 + j * 16],
                                        oacc[j], FP, wmma::mem_row_major);
        }
    }
    __syncthreads();

    // epilogue: g_attn = tf32(Os / l) — pre-rounded for the out-proj GEMM
    #pragma unroll
    for (int it = 0; it < 8; it++) {
        int u = tid + it * 256;
        int r = u >> 5, c = (u & 31) * 4;
        const float inv = 1.0f / lrow[r];
        float4 v = *(float4*)&Os[r * FP + c];
        v.x = wmma::__float_to_tf32(v.x * inv);
        v.y = wmma::__float_to_tf32(v.y * inv);
        v.z = wmma::__float_to_tf32(v.z * inv);
        v.w = wmma::__float_to_tf32(v.w * inv);
        float* Op = g_attn + ((size_t)b * SEQ + qt * 64 + r) * DM + h * DH + c;
        *(float4*)Op = v;
    }
}

// ---------------------------------------------------------------------------
extern "C" void kernel_launch(void* const* d_in, const int* in_sizes, int n_in,
                              void* d_out, int out_size)
{
    const float* x    = (const float*)d_in[0];
    const float* Wqkv = (const float*)d_in[1];
    const float* bqkv = (const float*)d_in[2];
    const float* Wout = (const float*)d_in[3];
    const float* bout = (const float*)d_in[4];
    float* out = (float*)d_out;

    const int M = BATCH * SEQ;  // 4096
    const int gemm_smem = 2 * STAGE_F * (int)sizeof(float);  // 75776 B

    cudaFuncSetAttribute(gemm_tf32_kernel<0>,
                         cudaFuncAttributeMaxDynamicSharedMemorySize, gemm_smem);
    cudaFuncSetAttribute(gemm_tf32_kernel<1>,
                         cudaFuncAttributeMaxDynamicSharedMemorySize, gemm_smem);

    // 0) pre-round GEMM inputs to tf32
    {
        float* xt; float* wq; float* wo;
        cudaGetSymbolAddress((void**)&xt, g_xt);
        cudaGetSymbolAddress((void**)&wq, g_wq);
        cudaGetSymbolAddress((void**)&wo, g_wo);
        cvt_tf32_kernel<<<(int)((size_t)BATCH*SEQ*DM/4/256), 256>>>(x, xt, (int)((size_t)BATCH*SEQ*DM/4));
        cvt_tf32_kernel<<<(int)((size_t)DM*3*DM/4/256), 256>>>(Wqkv, wq, (int)((size_t)DM*3*DM/4));
        cvt_tf32_kernel<<<(int)((size_t)DM*DM/4/256), 256>>>(Wout, wo, (int)((size_t)DM*DM/4));

        // 1) QKV projection (cp.async pipelined tf32), fused scatter
        {
            dim3 grid((3 * DM) / 128, M / 128);
            gemm_tf32_kernel<0><<<grid, 256, gemm_smem>>>(xt, wq, bqkv, nullptr, M, 3 * DM, DM);
        }
        // 2) causal flash attention -> g_attn (tf32-rounded)
        {
            const int smem = 38272 * (int)sizeof(float);  // 153088 B
            cudaFuncSetAttribute(flash_kernel,
                                 cudaFuncAttributeMaxDynamicSharedMemorySize, smem);
            dim3 grid(SEQ / 64, NH, BATCH);
            flash_kernel<<<grid, 256, smem>>>();
        }
        // 3) output projection -> d_out
        {
            dim3 grid(DM / 128, M / 128);
            gemm_tf32_kernel<1><<<grid, 256, gemm_smem>>>(nullptr, wo, bout, out, M, DM, DM);
        }
    }
}

// round 5
// speedup vs baseline: 2.2158x; 1.2063x over previous
#include <cuda_runtime.h>
#include <mma.h>
#include <math.h>
#include <stdint.h>

using namespace nvcuda;

#define BATCH 2
#define SEQ   2048
#define NH    16
#define DH    128
#define DM    2048
#define NQ    ((size_t)BATCH*NH*SEQ*DH)

__device__ float g_qkv[3*(size_t)BATCH*NH*SEQ*DH];
__device__ float g_attn[(size_t)BATCH*SEQ*DM];
__device__ float g_xt[(size_t)BATCH*SEQ*DM];
__device__ float g_wq[(size_t)DM*3*DM];
__device__ float g_wo[(size_t)DM*DM];

// ---------------------------------------------------------------------------
__device__ __forceinline__ uint32_t smem_u32(const void* p) {
    return (uint32_t)__cvta_generic_to_shared(p);
}
#define CP_ASYNC16(dst_u32, src_ptr) \
    asm volatile("cp.async.cg.shared.global [%0], [%1], 16;" :: "r"(dst_u32), "l"(src_ptr))
#define CP_COMMIT()   asm volatile("cp.async.commit_group;")
#define CP_WAIT(n)    asm volatile("cp.async.wait_group %0;" :: "n"(n))

// m16n8k8 tf32 mma, D += A*B (accumulate in place)
__device__ __forceinline__ void mma_tf32(float* d, const uint32_t* a, const uint32_t* b) {
    asm volatile(
        "mma.sync.aligned.m16n8k8.row.col.f32.tf32.tf32.f32 "
        "{%0,%1,%2,%3},{%4,%5,%6,%7},{%8,%9},{%0,%1,%2,%3};"
        : "+f"(d[0]), "+f"(d[1]), "+f"(d[2]), "+f"(d[3])
        : "r"(a[0]), "r"(a[1]), "r"(a[2]), "r"(a[3]), "r"(b[0]), "r"(b[1]));
}

// ---------------------------------------------------------------------------
// tf32 pre-rounding pass
// ---------------------------------------------------------------------------
__global__ void cvt_tf32_kernel(const float* __restrict__ in,
                                float* __restrict__ out, int n4)
{
    int i = blockIdx.x * blockDim.x + threadIdx.x;
    if (i < n4) {
        float4 v = ((const float4*)in)[i];
        v.x = wmma::__float_to_tf32(v.x); v.y = wmma::__float_to_tf32(v.y);
        v.z = wmma::__float_to_tf32(v.z); v.w = wmma::__float_to_tf32(v.w);
        ((float4*)out)[i] = v;
    }
}

// ---------------------------------------------------------------------------
// TF32 wmma GEMM with cp.async double-buffered pipeline (round-4 proven).
// MODE 0: scatter epilogue into g_qkv, values tf32-rounded for flash.
// MODE 1: row-major C (final output, fp32).
// ---------------------------------------------------------------------------
#define AS_PITCH 40
#define BS_PITCH 136
#define CS_PITCH 136
#define STAGE_F  (128*AS_PITCH + 32*BS_PITCH)   // 9472 floats

template<int MODE>
__global__ __launch_bounds__(256, 2)
void gemm_tf32_kernel(const float* __restrict__ Aglob, const float* __restrict__ B,
                      const float* __restrict__ bias, float* __restrict__ C,
                      int M, int N, int K)
{
    extern __shared__ float sm[];
    float* Cs = sm;

    const float* Abase = (MODE == 1) ? (const float*)g_attn : Aglob;

    const int tid  = threadIdx.x;
    const int warp = tid >> 5;
    const int wr   = warp >> 1;
    const int wc   = warp & 1;
    const int rowBlock = blockIdx.y * 128;
    const int colBlock = blockIdx.x * 128;

    const int aRow0 = tid >> 3;
    const int aCol  = (tid & 7) * 4;
    const int bRow0 = tid >> 5;
    const int bCol  = (tid & 31) * 4;

    const float* Asrc = Abase + (size_t)(rowBlock + aRow0) * K + aCol;
    const float* Bsrc = B + (size_t)bRow0 * N + colBlock + bCol;

    const uint32_t smBase = smem_u32(sm);
    const uint32_t aOffB  = (uint32_t)((aRow0 * AS_PITCH + aCol) * 4);
    const uint32_t bOffB  = (uint32_t)((128 * AS_PITCH + bRow0 * BS_PITCH + bCol) * 4);

    wmma::fragment<wmma::accumulator, 16, 16, 8, float> acc[2][4];
    #pragma unroll
    for (int i = 0; i < 2; i++)
        #pragma unroll
        for (int j = 0; j < 4; j++)
            wmma::fill_fragment(acc[i][j], 0.0f);

    const int NIT = K >> 5;

    auto issue = [&](int k0, int s) {
        const uint32_t sb = smBase + (uint32_t)(s * STAGE_F * 4);
        #pragma unroll
        for (int it = 0; it < 4; it++)
            CP_ASYNC16(sb + aOffB + (uint32_t)(it * 32 * AS_PITCH * 4),
                       Asrc + (size_t)(it * 32) * K + k0);
        #pragma unroll
        for (int it = 0; it < 4; it++)
            CP_ASYNC16(sb + bOffB + (uint32_t)(it * 8 * BS_PITCH * 4),
                       Bsrc + (size_t)(k0 + it * 8) * N);
    };

    issue(0, 0);
    CP_COMMIT();

    int buf = 0;
    for (int it = 0; it < NIT; it++) {
        if (it + 1 < NIT) {
            issue((it + 1) << 5, buf ^ 1);
            CP_COMMIT();
            CP_WAIT(1);
        } else {
            CP_WAIT(0);
        }
        __syncthreads();

        const float* As = sm + buf * STAGE_F;
        const float* Bs = As + 128 * AS_PITCH;
        #pragma unroll
        for (int ks = 0; ks < 4; ks++) {
            wmma::fragment<wmma::matrix_a, 16, 16, 8, wmma::precision::tf32, wmma::row_major> af[2];
            wmma::fragment<wmma::matrix_b, 16, 16, 8, wmma::precision::tf32, wmma::row_major> bf[4];
            #pragma unroll
            for (int i = 0; i < 2; i++)
                wmma::load_matrix_sync(af[i], &As[(wr * 32 + i * 16) * AS_PITCH + ks * 8], AS_PITCH);
            #pragma unroll
            for (int j = 0; j < 4; j++)
                wmma::load_matrix_sync(bf[j], &Bs[(ks * 8) * BS_PITCH + wc * 64 + j * 16], BS_PITCH);
            #pragma unroll
            for (int i = 0; i < 2; i++)
                #pragma unroll
                for (int j = 0; j < 4; j++)
                    wmma::mma_sync(acc[i][j], af[i], bf[j], acc[i][j]);
        }
        __syncthreads();
        buf ^= 1;
    }

    #pragma unroll
    for (int i = 0; i < 2; i++)
        #pragma unroll
        for (int j = 0; j < 4; j++)
            wmma::store_matrix_sync(&Cs[(wr * 32 + i * 16) * CS_PITCH + wc * 64 + j * 16],
                                    acc[i][j], CS_PITCH, wmma::mem_row_major);
    __syncthreads();

    #pragma unroll
    for (int it = 0; it < 16; it++) {
        int u = tid + it * 256;
        int row = u >> 5, c4 = (u & 31) * 4;
        float4 v = *(float4*)&Cs[row * CS_PITCH + c4];
        const int gcol = colBlock + c4;
        v.x += bias[gcol + 0]; v.y += bias[gcol + 1];
        v.z += bias[gcol + 2]; v.w += bias[gcol + 3];
        const int gr = rowBlock + row;
        if (MODE == 0) {
            // round for flash's tf32 consumers
            v.x = wmma::__float_to_tf32(v.x); v.y = wmma::__float_to_tf32(v.y);
            v.z = wmma::__float_to_tf32(v.z); v.w = wmma::__float_to_tf32(v.w);
            const int part = gcol >> 11;
            const int c2   = gcol & 2047;
            const int h    = c2 >> 7;
            const int d0   = c2 & 127;
            const int bb   = gr >> 11;
            const int s    = gr & 2047;
            float* dst = g_qkv + (size_t)part * NQ
                       + (((size_t)(bb * NH + h) * SEQ) + s) * DH + d0;
            *(float4*)dst = v;
        } else {
            *(float4*)(C + (size_t)gr * N + gcol) = v;
        }
    }
}

// ---------------------------------------------------------------------------
// Causal flash attention v2: raw m16n8k8 tf32 mma, O accumulator in registers,
// cp.async double-buffered K/V, scale folded into fp32 softmax.
// CTA = (b, h, 64-q tile), 256 threads, warp grid 4x2.
// Warp: S tile 16x32 (4 n-tiles), O tile 16x64 (8 n-tiles).
// ---------------------------------------------------------------------------
#define FP 132
#define SP 68

__global__ __launch_bounds__(256)
void flash_kernel()
{
    extern __shared__ float smf[];
    float* Qs  = smf;                          // 64*FP
    float* KsB[2] = { smf + 8448,  smf + 2*8448 };
    float* VsB[2] = { smf + 3*8448, smf + 4*8448 };
    float* Ss  = smf + 5*8448;                 // 64*SP
    float* mrow = Ss + 64*SP;                  // 64
    float* lrow = mrow + 64;
    float* arow = lrow + 64;

    const int qt = blockIdx.x, h = blockIdx.y, b = blockIdx.z;
    const int bh = b * NH + h;

    const float* Qp = g_qkv + 0 * NQ + ((size_t)bh * SEQ + qt * 64) * DH;
    const float* Kp = g_qkv + 1 * NQ + (size_t)bh * SEQ * DH;
    const float* Vp = g_qkv + 2 * NQ + (size_t)bh * SEQ * DH;

    const int tid  = threadIdx.x;
    const int warp = tid >> 5, lane = tid & 31;
    const int wr = warp >> 1, wc = warp & 1;
    const int g  = lane >> 2, tq = lane & 3;
    const int sr = wr * 16;

    const float scale = 0.08838834764831845f;

    // Q load (already tf32-rounded by gemm<0> epilogue)
    #pragma unroll
    for (int it = 0; it < 8; it++) {
        int u = tid + it * 256;
        int r = u >> 5, c = (u & 31) * 4;
        *(float4*)&Qs[r * FP + c] = *(const float4*)(Qp + r * DH + c);
    }
    if (tid < 64) { mrow[tid] = -1e30f; lrow[tid] = 0.f; }

    float oc[8][4];
    #pragma unroll
    for (int t = 0; t < 8; t++)
        #pragma unroll
        for (int i = 0; i < 4; i++) oc[t][i] = 0.f;

    // issue K/V for tile kt into buffer s
    auto issueKV = [&](int kt, int s) {
        const float* Kt = Kp + (size_t)kt * 64 * DH;
        const float* Vt = Vp + (size_t)kt * 64 * DH;
        float* Kd = KsB[s];
        float* Vd = VsB[s];
        #pragma unroll
        for (int it = 0; it < 8; it++) {
            int u = tid + it * 256;
            int r = u >> 5, c = (u & 31) * 4;
            CP_ASYNC16(smem_u32(&Kd[r * FP + c]), Kt + r * DH + c);
            CP_ASYNC16(smem_u32(&Vd[r * FP + c]), Vt + r * DH + c);
        }
    };

    issueKV(0, 0);
    CP_COMMIT();

    for (int kt = 0; kt <= qt; kt++) {
        const int buf = kt & 1;
        const float* Ks = KsB[buf];
        const float* Vs = VsB[buf];

        __syncthreads();                     // [A] prev PV reads done; buf^1 free
        if (kt < qt) {
            issueKV(kt + 1, buf ^ 1);
            CP_COMMIT();
            CP_WAIT(1);
        } else {
            CP_WAIT(0);
        }
        __syncthreads();                     // [B] K/V(kt) visible to all

        // ---- S = Q K^T : warp 16x32, 4 n-tiles, 16 k-steps ----
        {
            float sc[4][4] = {};
            const int sn0 = wc * 32;
            #pragma unroll
            for (int ks = 0; ks < 16; ks++) {
                const int k0 = ks * 8;
                uint32_t a[4];
                a[0] = __float_as_uint(Qs[(sr + g    ) * FP + k0 + tq    ]);
                a[1] = __float_as_uint(Qs[(sr + g + 8) * FP + k0 + tq    ]);
                a[2] = __float_as_uint(Qs[(sr + g    ) * FP + k0 + tq + 4]);
                a[3] = __float_as_uint(Qs[(sr + g + 8) * FP + k0 + tq + 4]);
                #pragma unroll
                for (int t = 0; t < 4; t++) {
                    uint32_t bf[2];
                    bf[0] = __float_as_uint(Ks[(sn0 + t * 8 + g) * FP + k0 + tq    ]);
                    bf[1] = __float_as_uint(Ks[(sn0 + t * 8 + g) * FP + k0 + tq + 4]);
                    mma_tf32(sc[t], a, bf);
                }
            }
            #pragma unroll
            for (int t = 0; t < 4; t++) {
                *(float2*)&Ss[(sr + g    ) * SP + sn0 + t * 8 + 2 * tq] =
                    make_float2(sc[t][0], sc[t][1]);
                *(float2*)&Ss[(sr + g + 8) * SP + sn0 + t * 8 + 2 * tq] =
                    make_float2(sc[t][2], sc[t][3]);
            }
        }
        __syncthreads();                     // [C]

        // ---- softmax (fp32): 4 lanes/row, scale applied here ----
        {
            const int row = tid >> 2;
            const int q4  = tid & 3;
            const int c0  = q4 * 16;
            float s[16];
            #pragma unroll
            for (int j = 0; j < 16; j++) {
                float v = Ss[row * SP + c0 + j] * scale;
                if (kt == qt && (c0 + j) > row) v = -1e30f;
                s[j] = v;
            }
            float mt = s[0];
            #pragma unroll
            for (int j = 1; j < 16; j++) mt = fmaxf(mt, s[j]);
            mt = fmaxf(mt, __shfl_xor_sync(0xffffffffu, mt, 1));
            mt = fmaxf(mt, __shfl_xor_sync(0xffffffffu, mt, 2));
            const float m_old = mrow[row];
            const float mnew  = fmaxf(m_old, mt);
            const float alpha = __expf(m_old - mnew);
            float rs = 0.f;
            #pragma unroll
            for (int j = 0; j < 16; j++) {
                float p = __expf(s[j] - mnew);
                rs += p;
                Ss[row * SP + c0 + j] = wmma::__float_to_tf32(p);
            }
            rs += __shfl_xor_sync(0xffffffffu, rs, 1);
            rs += __shfl_xor_sync(0xffffffffu, rs, 2);
            if (q4 == 0) {
                lrow[row] = lrow[row] * alpha + rs;
                mrow[row] = mnew;
                arow[row] = alpha;
            }
        }
        __syncthreads();                     // [D]

        // ---- O = O*alpha + P V : warp 16x64, 8 n-tiles, 8 k-steps ----
        {
            const float a_lo = arow[sr + g], a_hi = arow[sr + g + 8];
            #pragma unroll
            for (int t = 0; t < 8; t++) {
                oc[t][0] *= a_lo; oc[t][1] *= a_lo;
                oc[t][2] *= a_hi; oc[t][3] *= a_hi;
            }
            const int on0 = wc * 64;
            #pragma unroll
            for (int ks = 0; ks < 8; ks++) {
                const int k0 = ks * 8;
                uint32_t a[4];
                a[0] = __float_as_uint(Ss[(sr + g    ) * SP + k0 + tq    ]);
                a[1] = __float_as_uint(Ss[(sr + g + 8) * SP + k0 + tq    ]);
                a[2] = __float_as_uint(Ss[(sr + g    ) * SP + k0 + tq + 4]);
                a[3] = __float_as_uint(Ss[(sr + g + 8) * SP + k0 + tq + 4]);
                #pragma unroll
                for (int t = 0; t < 8; t++) {
                    uint32_t bf[2];
                    bf[0] = __float_as_uint(Vs[(k0 + tq    ) * FP + on0 + t * 8 + g]);
                    bf[1] = __float_as_uint(Vs[(k0 + tq + 4) * FP + on0 + t * 8 + g]);
                    mma_tf32(oc[t], a, bf);
                }
            }
        }
    }
    __syncthreads();

    // epilogue: g_attn = tf32(O / l)
    {
        const int on0 = wc * 64;
        const float inv_lo = 1.0f / lrow[sr + g];
        const float inv_hi = 1.0f / lrow[sr + g + 8];
        float* Obase = g_attn + ((size_t)b * SEQ + qt * 64) * DM + h * DH;
        #pragma unroll
        for (int t = 0; t < 8; t++) {
            const int col = on0 + t * 8 + 2 * tq;
            float2 lo = make_float2(wmma::__float_to_tf32(oc[t][0] * inv_lo),
                                    wmma::__float_to_tf32(oc[t][1] * inv_lo));
            float2 hi = make_float2(wmma::__float_to_tf32(oc[t][2] * inv_hi),
                                    wmma::__float_to_tf32(oc[t][3] * inv_hi));
            *(float2*)(Obase + (size_t)(sr + g    ) * DM + col) = lo;
            *(float2*)(Obase + (size_t)(sr + g + 8) * DM + col) = hi;
        }
    }
}

// ---------------------------------------------------------------------------
extern "C" void kernel_launch(void* const* d_in, const int* in_sizes, int n_in,
                              void* d_out, int out_size)
{
    const float* x    = (const float*)d_in[0];
    const float* Wqkv = (const float*)d_in[1];
    const float* bqkv = (const float*)d_in[2];
    const float* Wout = (const float*)d_in[3];
    const float* bout = (const float*)d_in[4];
    float* out = (float*)d_out;

    const int M = BATCH * SEQ;
    const int gemm_smem = 2 * STAGE_F * (int)sizeof(float);   // 75776 B

    cudaFuncSetAttribute(gemm_tf32_kernel<0>,
                         cudaFuncAttributeMaxDynamicSharedMemorySize, gemm_smem);
    cudaFuncSetAttribute(gemm_tf32_kernel<1>,
                         cudaFuncAttributeMaxDynamicSharedMemorySize, gemm_smem);

    float* xt; float* wq; float* wo;
    cudaGetSymbolAddress((void**)&xt, g_xt);
    cudaGetSymbolAddress((void**)&wq, g_wq);
    cudaGetSymbolAddress((void**)&wo, g_wo);

    // 0) pre-round GEMM inputs to tf32
    cvt_tf32_kernel<<<(int)((size_t)BATCH*SEQ*DM/4/256), 256>>>(x, xt, (int)((size_t)BATCH*SEQ*DM/4));
    cvt_tf32_kernel<<<(int)((size_t)DM*3*DM/4/256), 256>>>(Wqkv, wq, (int)((size_t)DM*3*DM/4));
    cvt_tf32_kernel<<<(int)((size_t)DM*DM/4/256), 256>>>(Wout, wo, (int)((size_t)DM*DM/4));

    // 1) QKV projection (cp.async tf32), scatter epilogue (tf32-rounded)
    {
        dim3 grid((3 * DM) / 128, M / 128);
        gemm_tf32_kernel<0><<<grid, 256, gemm_smem>>>(xt, wq, bqkv, nullptr, M, 3 * DM, DM);
    }
    // 2) flash attention v2 (raw mma, O in regs, cp.async K/V)
    {
        const int smem = (5 * 8448 + 64 * SP + 192) * (int)sizeof(float);  // 187136 B
        cudaFuncSetAttribute(flash_kernel,
                             cudaFuncAttributeMaxDynamicSharedMemorySize, smem);
        dim3 grid(SEQ / 64, NH, BATCH);
        flash_kernel<<<grid, 256, smem>>>();
    }
    // 3) output projection -> d_out (fp32 result)
    {
        dim3 grid(DM / 128, M / 128);
        gemm_tf32_kernel<1><<<grid, 256, gemm_smem>>>(nullptr, wo, bout, out, M, DM, DM);
    }
}

// round 7
// speedup vs baseline: 2.2859x; 1.0316x over previous
#include <cuda_runtime.h>
#include <mma.h>
#include <math.h>
#include <stdint.h>

using namespace nvcuda;

#define BATCH 2
#define SEQ   2048
#define NH    16
#define DH    128
#define DM    2048
#define NQ    ((size_t)BATCH*NH*SEQ*DH)

__device__ float g_qkv[3*(size_t)BATCH*NH*SEQ*DH];
__device__ float g_attn[(size_t)BATCH*SEQ*DM];
__device__ float g_xt[(size_t)BATCH*SEQ*DM];
__device__ float g_wq[(size_t)DM*3*DM];
__device__ float g_wo[(size_t)DM*DM];

// ---------------------------------------------------------------------------
__device__ __forceinline__ uint32_t smem_u32(const void* p) {
    return (uint32_t)__cvta_generic_to_shared(p);
}
#define CP_ASYNC16(dst_u32, src_ptr) \
    asm volatile("cp.async.cg.shared.global [%0], [%1], 16;" :: "r"(dst_u32), "l"(src_ptr))
#define CP_COMMIT()   asm volatile("cp.async.commit_group;")
#define CP_WAIT(n)    asm volatile("cp.async.wait_group %0;" :: "n"(n))

// m16n8k8 tf32 mma, D += A*B
__device__ __forceinline__ void mma_tf32(float* d, const uint32_t* a, const uint32_t* b) {
    asm volatile(
        "mma.sync.aligned.m16n8k8.row.col.f32.tf32.tf32.f32 "
        "{%0,%1,%2,%3},{%4,%5,%6,%7},{%8,%9},{%0,%1,%2,%3};"
        : "+f"(d[0]), "+f"(d[1]), "+f"(d[2]), "+f"(d[3])
        : "r"(a[0]), "r"(a[1]), "r"(a[2]), "r"(a[3]), "r"(b[0]), "r"(b[1]));
}

// ---------------------------------------------------------------------------
// tf32 pre-rounding pass
// ---------------------------------------------------------------------------
__global__ void cvt_tf32_kernel(const float* __restrict__ in,
                                float* __restrict__ out, int n4)
{
    int i = blockIdx.x * blockDim.x + threadIdx.x;
    if (i < n4) {
        float4 v = ((const float4*)in)[i];
        v.x = wmma::__float_to_tf32(v.x); v.y = wmma::__float_to_tf32(v.y);
        v.z = wmma::__float_to_tf32(v.z); v.w = wmma::__float_to_tf32(v.w);
        ((float4*)out)[i] = v;
    }
}

// ---------------------------------------------------------------------------
// TF32 wmma GEMM, 3-stage cp.async pipeline, ONE sync per K-tile.
// C[M,N] = A[M,K] @ B[K,N] + bias. 128x128 tile, BK=32, 256 thr (8 warps 4x2).
// MODE 0: A=g_xt, scatter epilogue into g_qkv (tf32-rounded).
// MODE 1: A=g_attn, row-major fp32 C.
// ---------------------------------------------------------------------------
#define AS_PITCH 36
#define BS_PITCH 132
#define CS_PITCH 132
#define STAGE_F  (128*AS_PITCH + 32*BS_PITCH)   // 8832 floats = 35328 B
#define GEMM_SMEM (3*STAGE_F*4)                 // 105984 B

template<int MODE>
__global__ __launch_bounds__(256, 2)
void gemm_tf32_kernel(const float* __restrict__ Aglob, const float* __restrict__ B,
                      const float* __restrict__ bias, float* __restrict__ C,
                      int M, int N, int K)
{
    extern __shared__ float sm[];
    float* Cs = sm;   // epilogue reuse: 128*132 = 16896 floats (< 2 stages)

    const float* Abase = (MODE == 1) ? (const float*)g_attn : Aglob;

    const int tid  = threadIdx.x;
    const int warp = tid >> 5;
    const int wr   = warp >> 1;
    const int wc   = warp & 1;
    const int rowBlock = blockIdx.y * 128;
    const int colBlock = blockIdx.x * 128;

    const int aRow0 = tid >> 3;
    const int aCol  = (tid & 7) * 4;
    const int bRow0 = tid >> 5;
    const int bCol  = (tid & 31) * 4;

    const float* Asrc = Abase + (size_t)(rowBlock + aRow0) * K + aCol;
    const float* Bsrc = B + (size_t)bRow0 * N + colBlock + bCol;

    const uint32_t smBase = smem_u32(sm);
    const uint32_t aOffB  = (uint32_t)((aRow0 * AS_PITCH + aCol) * 4);
    const uint32_t bOffB  = (uint32_t)((128 * AS_PITCH + bRow0 * BS_PITCH + bCol) * 4);

    wmma::fragment<wmma::accumulator, 16, 16, 8, float> acc[2][4];
    #pragma unroll
    for (int i = 0; i < 2; i++)
        #pragma unroll
        for (int j = 0; j < 4; j++)
            wmma::fill_fragment(acc[i][j], 0.0f);

    const int NIT = K >> 5;

    auto issue = [&](int tt, int s) {
        const int k0 = tt << 5;
        const uint32_t sb = smBase + (uint32_t)s * (STAGE_F * 4);
        #pragma unroll
        for (int it = 0; it < 4; it++)
            CP_ASYNC16(sb + aOffB + (uint32_t)(it * 32 * AS_PITCH * 4),
                       Asrc + (size_t)(it * 32) * K + k0);
        #pragma unroll
        for (int it = 0; it < 4; it++)
            CP_ASYNC16(sb + bOffB + (uint32_t)(it * 8 * BS_PITCH * 4),
                       Bsrc + (size_t)(k0 + it * 8) * N);
        CP_COMMIT();
    };

    issue(0, 0);

    for (int t = 0; t < NIT; t++) {
        if (t + 1 < NIT) {
            issue(t + 1, (t + 1) % 3);
            CP_WAIT(1);
        } else {
            CP_WAIT(0);
        }
        __syncthreads();   // tile t visible; orders stage reuse (distance-2)

        const float* As = sm + (t % 3) * STAGE_F;
        const float* Bs = As + 128 * AS_PITCH;
        #pragma unroll
        for (int ks = 0; ks < 4; ks++) {
            wmma::fragment<wmma::matrix_a, 16, 16, 8, wmma::precision::tf32, wmma::row_major> af[2];
            wmma::fragment<wmma::matrix_b, 16, 16, 8, wmma::precision::tf32, wmma::row_major> bf[4];
            #pragma unroll
            for (int i = 0; i < 2; i++)
                wmma::load_matrix_sync(af[i], &As[(wr * 32 + i * 16) * AS_PITCH + ks * 8], AS_PITCH);
            #pragma unroll
            for (int j = 0; j < 4; j++)
                wmma::load_matrix_sync(bf[j], &Bs[(ks * 8) * BS_PITCH + wc * 64 + j * 16], BS_PITCH);
            #pragma unroll
            for (int i = 0; i < 2; i++)
                #pragma unroll
                for (int j = 0; j < 4; j++)
                    wmma::mma_sync(acc[i][j], af[i], bf[j], acc[i][j]);
        }
    }
    __syncthreads();   // all warps done with smem stages before Cs reuse

    #pragma unroll
    for (int i = 0; i < 2; i++)
        #pragma unroll
        for (int j = 0; j < 4; j++)
            wmma::store_matrix_sync(&Cs[(wr * 32 + i * 16) * CS_PITCH + wc * 64 + j * 16],
                                    acc[i][j], CS_PITCH, wmma::mem_row_major);
    __syncthreads();

    #pragma unroll
    for (int it = 0; it < 16; it++) {
        int u = tid + it * 256;
        int row = u >> 5, c4 = (u & 31) * 4;
        float4 v = *(float4*)&Cs[row * CS_PITCH + c4];
        const int gcol = colBlock + c4;
        v.x += bias[gcol + 0]; v.y += bias[gcol + 1];
        v.z += bias[gcol + 2]; v.w += bias[gcol + 3];
        const int gr = rowBlock + row;
        if (MODE == 0) {
            v.x = wmma::__float_to_tf32(v.x); v.y = wmma::__float_to_tf32(v.y);
            v.z = wmma::__float_to_tf32(v.z); v.w = wmma::__float_to_tf32(v.w);
            const int part = gcol >> 11;
            const int c2   = gcol & 2047;
            const int h    = c2 >> 7;
            const int d0   = c2 & 127;
            const int bb   = gr >> 11;
            const int s    = gr & 2047;
            float* dst = g_qkv + (size_t)part * NQ
                       + (((size_t)(bb * NH + h) * SEQ) + s) * DH + d0;
            *(float4*)dst = v;
        } else {
            *(float4*)(C + (size_t)gr * N + gcol) = v;
        }
    }
}

// ---------------------------------------------------------------------------
// Causal flash attention v3: Q fragments resident in registers, 3-stage
// cp.async K/V ring, 3 syncs per kt-iter.
// CTA = (b, h, 64-q tile), 256 threads, warp grid 4x2.
// smem: stage s in [s*2*8448, +2*8448): K then V (pitch FP). Ss after stage 2.
// ---------------------------------------------------------------------------
#define FP 132
#define SP 68
#define KVSTRIDE (2*8448)
#define FLASH_SMEM ((6*8448 + 64*SP + 192) * 4)   // 220928 B

__global__ __launch_bounds__(256)
void flash_kernel()
{
    extern __shared__ float smf[];
    float* Ss   = smf + 6 * 8448;
    float* mrow = Ss + 64 * SP;
    float* lrow = mrow + 64;
    float* arow = lrow + 64;

    const int qt = blockIdx.x, h = blockIdx.y, b = blockIdx.z;
    const int bh = b * NH + h;

    const float* Qp = g_qkv + 0 * NQ + ((size_t)bh * SEQ + qt * 64) * DH;
    const float* Kp = g_qkv + 1 * NQ + (size_t)bh * SEQ * DH;
    const float* Vp = g_qkv + 2 * NQ + (size_t)bh * SEQ * DH;

    const int tid  = threadIdx.x;
    const int warp = tid >> 5, lane = tid & 31;
    const int wr = warp >> 1, wc = warp & 1;
    const int g  = lane >> 2, tq = lane & 3;
    const int sr = wr * 16;

    const float scale = 0.08838834764831845f;

    auto issueKV = [&](int kt, int s) {
        const float* Kt = Kp + (size_t)kt * 64 * DH;
        const float* Vt = Vp + (size_t)kt * 64 * DH;
        float* Kd = smf + s * KVSTRIDE;
        float* Vd = Kd + 8448;
        #pragma unroll
        for (int it = 0; it < 8; it++) {
            int u = tid + it * 256;
            int r = u >> 5, c = (u & 31) * 4;
            CP_ASYNC16(smem_u32(&Kd[r * FP + c]), Kt + r * DH + c);
            CP_ASYNC16(smem_u32(&Vd[r * FP + c]), Vt + r * DH + c);
        }
        CP_COMMIT();
    };

    // start KV(0) load, stage Q into stage-2 V buffer (free until iter 1)
    issueKV(0, 0);
    {
        float* Qtmp = smf + 2 * KVSTRIDE + 8448;
        #pragma unroll
        for (int it = 0; it < 8; it++) {
            int u = tid + it * 256;
            int r = u >> 5, c = (u & 31) * 4;
            *(float4*)&Qtmp[r * FP + c] = *(const float4*)(Qp + r * DH + c);
        }
    }
    if (tid < 64) { mrow[tid] = -1e30f; lrow[tid] = 0.f; }
    __syncthreads();

    // Q fragments -> registers (invariant across kt loop)
    uint32_t qf[16][4];
    {
        const float* Qtmp = smf + 2 * KVSTRIDE + 8448;
        #pragma unroll
        for (int ks = 0; ks < 16; ks++) {
            const int k0 = ks * 8;
            qf[ks][0] = __float_as_uint(Qtmp[(sr + g    ) * FP + k0 + tq    ]);
            qf[ks][1] = __float_as_uint(Qtmp[(sr + g + 8) * FP + k0 + tq    ]);
            qf[ks][2] = __float_as_uint(Qtmp[(sr + g    ) * FP + k0 + tq + 4]);
            qf[ks][3] = __float_as_uint(Qtmp[(sr + g + 8) * FP + k0 + tq + 4]);
        }
    }

    float oc[8][4];
    #pragma unroll
    for (int t = 0; t < 8; t++)
        #pragma unroll
        for (int i = 0; i < 4; i++) oc[t][i] = 0.f;

    for (int kt = 0; kt <= qt; kt++) {
        const float* Ks = smf + (kt % 3) * KVSTRIDE;
        const float* Vs = Ks + 8448;

        if (kt < qt) {
            issueKV(kt + 1, (kt + 1) % 3);
            CP_WAIT(1);
        } else {
            CP_WAIT(0);
        }
        __syncthreads();                     // [B] KV(kt) visible; orders everything

        // ---- S = Q K^T : warp 16x32, Q from registers ----
        {
            float sc[4][4] = {};
            const int sn0 = wc * 32;
            #pragma unroll
            for (int ks = 0; ks < 16; ks++) {
                const int k0 = ks * 8;
                #pragma unroll
                for (int t = 0; t < 4; t++) {
                    uint32_t bf[2];
                    bf[0] = __float_as_uint(Ks[(sn0 + t * 8 + g) * FP + k0 + tq    ]);
                    bf[1] = __float_as_uint(Ks[(sn0 + t * 8 + g) * FP + k0 + tq + 4]);
                    mma_tf32(sc[t], qf[ks], bf);
                }
            }
            #pragma unroll
            for (int t = 0; t < 4; t++) {
                *(float2*)&Ss[(sr + g    ) * SP + sn0 + t * 8 + 2 * tq] =
                    make_float2(sc[t][0], sc[t][1]);
                *(float2*)&Ss[(sr + g + 8) * SP + sn0 + t * 8 + 2 * tq] =
                    make_float2(sc[t][2], sc[t][3]);
            }
        }
        __syncthreads();                     // [C]

        // ---- softmax (fp32): 4 lanes/row ----
        {
            const int row = tid >> 2;
            const int q4  = tid & 3;
            const int c0  = q4 * 16;
            float s[16];
            #pragma unroll
            for (int j = 0; j < 16; j++) {
                float v = Ss[row * SP + c0 + j] * scale;
                if (kt == qt && (c0 + j) > row) v = -1e30f;
                s[j] = v;
            }
            float mt = s[0];
            #pragma unroll
            for (int j = 1; j < 16; j++) mt = fmaxf(mt, s[j]);
            mt = fmaxf(mt, __shfl_xor_sync(0xffffffffu, mt, 1));
            mt = fmaxf(mt, __shfl_xor_sync(0xffffffffu, mt, 2));
            const float m_old = mrow[row];
            const float mnew  = fmaxf(m_old, mt);
            const float alpha = __expf(m_old - mnew);
            float rs = 0.f;
            #pragma unroll
            for (int j = 0; j < 16; j++) {
                float p = __expf(s[j] - mnew);
                rs += p;
                Ss[row * SP + c0 + j] = wmma::__float_to_tf32(p);
            }
            rs += __shfl_xor_sync(0xffffffffu, rs, 1);
            rs += __shfl_xor_sync(0xffffffffu, rs, 2);
            if (q4 == 0) {
                lrow[row] = lrow[row] * alpha + rs;
                mrow[row] = mnew;
                arow[row] = alpha;
            }
        }
        __syncthreads();                     // [D]

        // ---- O = O*alpha + P V : warp 16x64 ----
        {
            const float a_lo = arow[sr + g], a_hi = arow[sr + g + 8];
            #pragma unroll
            for (int t = 0; t < 8; t++) {
                oc[t][0] *= a_lo; oc[t][1] *= a_lo;
                oc[t][2] *= a_hi; oc[t][3] *= a_hi;
            }
            const int on0 = wc * 64;
            #pragma unroll
            for (int ks = 0; ks < 8; ks++) {
                const int k0 = ks * 8;
                uint32_t a[4];
                a[0] = __float_as_uint(Ss[(sr + g    ) * SP + k0 + tq    ]);
                a[1] = __float_as_uint(Ss[(sr + g + 8) * SP + k0 + tq    ]);
                a[2] = __float_as_uint(Ss[(sr + g    ) * SP + k0 + tq + 4]);
                a[3] = __float_as_uint(Ss[(sr + g + 8) * SP + k0 + tq + 4]);
                #pragma unroll
                for (int t = 0; t < 8; t++) {
                    uint32_t bf[2];
                    bf[0] = __float_as_uint(Vs[(k0 + tq    ) * FP + on0 + t * 8 + g]);
                    bf[1] = __float_as_uint(Vs[(k0 + tq + 4) * FP + on0 + t * 8 + g]);
                    mma_tf32(oc[t], a, bf);
                }
            }
        }
    }
    __syncthreads();

    // epilogue: g_attn = tf32(O / l)
    {
        const int on0 = wc * 64;
        const float inv_lo = 1.0f / lrow[sr + g];
        const float inv_hi = 1.0f / lrow[sr + g + 8];
        float* Obase = g_attn + ((size_t)b * SEQ + qt * 64) * DM + h * DH;
        #pragma unroll
        for (int t = 0; t < 8; t++) {
            const int col = on0 + t * 8 + 2 * tq;
            float2 lo = make_float2(wmma::__float_to_tf32(oc[t][0] * inv_lo),
                                    wmma::__float_to_tf32(oc[t][1] * inv_lo));
            float2 hi = make_float2(wmma::__float_to_tf32(oc[t][2] * inv_hi),
                                    wmma::__float_to_tf32(oc[t][3] * inv_hi));
            *(float2*)(Obase + (size_t)(sr + g    ) * DM + col) = lo;
            *(float2*)(Obase + (size_t)(sr + g + 8) * DM + col) = hi;
        }
    }
}

// ---------------------------------------------------------------------------
extern "C" void kernel_launch(void* const* d_in, const int* in_sizes, int n_in,
                              void* d_out, int out_size)
{
    const float* x    = (const float*)d_in[0];
    const float* Wqkv = (const float*)d_in[1];
    const float* bqkv = (const float*)d_in[2];
    const float* Wout = (const float*)d_in[3];
    const float* bout = (const float*)d_in[4];
    float* out = (float*)d_out;

    const int M = BATCH * SEQ;

    cudaFuncSetAttribute(gemm_tf32_kernel<0>,
                         cudaFuncAttributeMaxDynamicSharedMemorySize, GEMM_SMEM);
    cudaFuncSetAttribute(gemm_tf32_kernel<1>,
                         cudaFuncAttributeMaxDynamicSharedMemorySize, GEMM_SMEM);
    cudaFuncSetAttribute(flash_kernel,
                         cudaFuncAttributeMaxDynamicSharedMemorySize, FLASH_SMEM);

    float* xt; float* wq; float* wo;
    cudaGetSymbolAddress((void**)&xt, g_xt);
    cudaGetSymbolAddress((void**)&wq, g_wq);
    cudaGetSymbolAddress((void**)&wo, g_wo);

    // 0) pre-round GEMM inputs to tf32
    cvt_tf32_kernel<<<(int)((size_t)BATCH*SEQ*DM/4/256), 256>>>(x, xt, (int)((size_t)BATCH*SEQ*DM/4));
    cvt_tf32_kernel<<<(int)((size_t)DM*3*DM/4/256), 256>>>(Wqkv, wq, (int)((size_t)DM*3*DM/4));
    cvt_tf32_kernel<<<(int)((size_t)DM*DM/4/256), 256>>>(Wout, wo, (int)((size_t)DM*DM/4));

    // 1) QKV projection (3-stage cp.async tf32), scatter epilogue
    {
        dim3 grid((3 * DM) / 128, M / 128);
        gemm_tf32_kernel<0><<<grid, 256, GEMM_SMEM>>>(xt, wq, bqkv, nullptr, M, 3 * DM, DM);
    }
    // 2) flash attention v3 (Q in regs, 3-stage KV)
    {
        dim3 grid(SEQ / 64, NH, BATCH);
        flash_kernel<<<grid, 256, FLASH_SMEM>>>();
    }
    // 3) output projection -> d_out
    {
        dim3 grid(DM / 128, M / 128);
        gemm_tf32_kernel<1><<<grid, 256, GEMM_SMEM>>>(nullptr, wo, bout, out, M, DM, DM);
    }
}